// round 9
// baseline (speedup 1.0000x reference)
#include <cuda_runtime.h>
#include <cstdint>

// ---------------------------------------------------------------------------
// FCOS decoder heads, fp32 baseline.
// 5 FPN levels (128^2..8^2), batch 4, C=256.
// Per head: 4x [conv3x3(256->256) -> BN(scale,bias) -> ReLU], then 1x1 conv.
// cls head -> 80 ch (raw logits + bias)
// reg head -> 5 ch: ch0 = centerness (raw), ch1..4 = max(raw*stride, 0)
// Output order: cls0..4, reg0..4, ctr0..4 (each NCHW, flattened).
// ---------------------------------------------------------------------------

#define ICH 256
#define OCH 256
#define NB  4

// Scratch (no cudaMalloc allowed): ping-pong activation buffers sized for the
// largest level, transposed conv weights, transposed cls-final weights.
__device__ float g_bufA[(size_t)NB * ICH * 128 * 128];   // 64 MiB
__device__ float g_bufB[(size_t)NB * ICH * 128 * 128];   // 64 MiB
__device__ float g_wT[(size_t)2 * 4 * 9 * ICH * OCH];    // [head][layer][ic][tap][oc]
__device__ float g_wfc[80 * 256];                        // cls final, [ic][oc]

// ---------------------------------------------------------------------------
// Weight transpose: (4, OC, IC, 3, 3) -> (4, IC, 9, OC)
// ---------------------------------------------------------------------------
__global__ void transpose_weights(const float* __restrict__ w,
                                  float* __restrict__ wT) {
    long i = (long)blockIdx.x * blockDim.x + threadIdx.x;
    const long total = 4L * ICH * 9 * OCH;
    if (i >= total) return;
    int oc = (int)(i & (OCH - 1));
    long t = i >> 8;
    int tap = (int)(t % 9); t /= 9;
    int ic = (int)(t & (ICH - 1)); t >>= 8;
    int layer = (int)t;
    wT[i] = w[(((long)(layer * OCH + oc) * ICH + ic) * 9) + tap];
}

// cls final weights: (80, 256) -> (256, 80)
__global__ void transpose_fc(const float* __restrict__ w,
                             float* __restrict__ wT) {
    int i = blockIdx.x * blockDim.x + threadIdx.x;
    if (i >= 80 * 256) return;
    int oc = i % 80;
    int ic = i / 80;
    wT[i] = w[oc * 256 + ic];
}

// ---------------------------------------------------------------------------
// conv3x3 + BN + ReLU.
// Block: 64 output channels x 8x8 spatial tile, 256 threads, 4x4 reg tile.
// wT layout: [ic][tap][oc] (per-layer slice passed in).
// ---------------------------------------------------------------------------
__global__ __launch_bounds__(256)
void conv3x3_bn_relu(const float* __restrict__ in,
                     const float* __restrict__ wT,
                     const float* __restrict__ scale,
                     const float* __restrict__ bias,
                     float* __restrict__ out,
                     int H, int W) {
    __shared__ __align__(16) float sW[16 * 9 * 64];   // [icl][tap][oc64]
    __shared__ float sIn[16 * 100];                   // [icl][10][10]

    const int tid = threadIdx.x;
    const int tilesX = W >> 3;
    const int tileX = blockIdx.x % tilesX;
    const int tileY = blockIdx.x / tilesX;
    const int ocb = blockIdx.y << 6;
    const int n = blockIdx.z;
    const int gx0 = tileX << 3;
    const int gy0 = tileY << 3;

    const int ocq = tid >> 4;           // 0..15 (group of 4 oc)
    const int pg  = tid & 15;           // 0..15 (group of 4 px)
    const int row = pg >> 1;            // 0..7
    const int col = (pg & 1) << 2;      // 0 or 4

    float acc[4][4];
#pragma unroll
    for (int i = 0; i < 4; ++i)
#pragma unroll
        for (int j = 0; j < 4; ++j) acc[i][j] = 0.f;

    const float* inN = in + (size_t)n * ICH * H * W;

    for (int ic0 = 0; ic0 < ICH; ic0 += 16) {
        // load input halo tile: 16 x 10 x 10, zero-padded at borders
        for (int i = tid; i < 1600; i += 256) {
            int icl = i / 100;
            int r = i - icl * 100;
            int y = r / 10;
            int x = r - y * 10;
            int gy = gy0 + y - 1;
            int gx = gx0 + x - 1;
            float v = 0.f;
            if ((unsigned)gy < (unsigned)H && (unsigned)gx < (unsigned)W)
                v = inN[((size_t)(ic0 + icl) * H + gy) * W + gx];
            sIn[i] = v;
        }
        // load weights: 16 x 9 x 64, coalesced over oc
        for (int i = tid; i < 9216; i += 256) {
            int icl = i / 576;
            int r = i - icl * 576;
            int tap = r >> 6;
            int oc = r & 63;
            sW[i] = wT[(((size_t)(ic0 + icl) * 9 + tap) << 8) + ocb + oc];
        }
        __syncthreads();

#pragma unroll 2
        for (int icl = 0; icl < 16; ++icl) {
#pragma unroll
            for (int ky = 0; ky < 3; ++ky) {
#pragma unroll
                for (int kx = 0; kx < 3; ++kx) {
                    const int tap = ky * 3 + kx;
                    float4 a4 = *(const float4*)(sW + (icl * 9 + tap) * 64 + (ocq << 2));
                    const float* bp = sIn + icl * 100 + (row + ky) * 10 + col + kx;
                    float b0 = bp[0], b1 = bp[1], b2 = bp[2], b3 = bp[3];
                    acc[0][0] = fmaf(a4.x, b0, acc[0][0]);
                    acc[0][1] = fmaf(a4.x, b1, acc[0][1]);
                    acc[0][2] = fmaf(a4.x, b2, acc[0][2]);
                    acc[0][3] = fmaf(a4.x, b3, acc[0][3]);
                    acc[1][0] = fmaf(a4.y, b0, acc[1][0]);
                    acc[1][1] = fmaf(a4.y, b1, acc[1][1]);
                    acc[1][2] = fmaf(a4.y, b2, acc[1][2]);
                    acc[1][3] = fmaf(a4.y, b3, acc[1][3]);
                    acc[2][0] = fmaf(a4.z, b0, acc[2][0]);
                    acc[2][1] = fmaf(a4.z, b1, acc[2][1]);
                    acc[2][2] = fmaf(a4.z, b2, acc[2][2]);
                    acc[2][3] = fmaf(a4.z, b3, acc[2][3]);
                    acc[3][0] = fmaf(a4.w, b0, acc[3][0]);
                    acc[3][1] = fmaf(a4.w, b1, acc[3][1]);
                    acc[3][2] = fmaf(a4.w, b2, acc[3][2]);
                    acc[3][3] = fmaf(a4.w, b3, acc[3][3]);
                }
            }
        }
        __syncthreads();
    }

    // epilogue: BN fold + ReLU
    const size_t HW = (size_t)H * W;
    const size_t base = ((size_t)n * OCH + ocb + (ocq << 2)) * HW;
#pragma unroll
    for (int i = 0; i < 4; ++i) {
        const int oc = ocb + (ocq << 2) + i;
        const float sc = scale[oc];
        const float bi = bias[oc];
        const size_t rbase = base + (size_t)i * HW + (size_t)(gy0 + row) * W + gx0 + col;
#pragma unroll
        for (int j = 0; j < 4; ++j) {
            float v = fmaf(acc[i][j], sc, bi);
            out[rbase + j] = fmaxf(v, 0.f);
        }
    }
}

// ---------------------------------------------------------------------------
// cls final: 1x1 conv 256 -> 80 (+bias). Block: 32 pixels, 8 groups x 10 oc.
// wT layout [ic][80].
// ---------------------------------------------------------------------------
__global__ __launch_bounds__(256)
void final_conv_cls(const float* __restrict__ in,
                    const float* __restrict__ wT,
                    const float* __restrict__ b,
                    float* __restrict__ out, int HW) {
    __shared__ float xs[8192];       // [ic(256)][px(32)]
    __shared__ float ws[32 * 80];    // chunk of 32 ic x 80 oc

    const int tid = threadIdx.x;
    const long p0 = (long)blockIdx.x * 32;
    const int n = (int)(p0 / HW);
    const int s0 = (int)(p0 % HW);
    const float* inN = in + (size_t)n * 256 * HW + s0;

    for (int i = tid; i < 8192; i += 256) {
        int ic = i >> 5, p = i & 31;
        xs[i] = inN[(size_t)ic * HW + p];
    }

    const int px = tid & 31;
    const int g = tid >> 5;
    const int oc0 = g * 10;
    float acc[10];
#pragma unroll
    for (int j = 0; j < 10; ++j) acc[j] = b[oc0 + j];

    for (int ic0 = 0; ic0 < 256; ic0 += 32) {
        __syncthreads();
        for (int i = tid; i < 2560; i += 256) ws[i] = wT[ic0 * 80 + i];
        __syncthreads();
        for (int icc = 0; icc < 32; ++icc) {
            float x = xs[((ic0 + icc) << 5) + px];
            const float* wr = &ws[icc * 80 + oc0];
#pragma unroll
            for (int j = 0; j < 10; ++j) acc[j] = fmaf(x, wr[j], acc[j]);
        }
    }

    const int s = s0 + px;
#pragma unroll
    for (int j = 0; j < 10; ++j)
        out[((size_t)n * 80 + oc0 + j) * HW + s] = acc[j];
}

// ---------------------------------------------------------------------------
// reg final: 1x1 conv 256 -> 5 (+bias). ch0 -> centerness (raw),
// ch1..4 -> max(raw * stride, 0). w layout [oc(5)][ic(256)].
// ---------------------------------------------------------------------------
__global__ __launch_bounds__(256)
void final_conv_reg(const float* __restrict__ in,
                    const float* __restrict__ w,
                    const float* __restrict__ b,
                    float* __restrict__ out_reg,
                    float* __restrict__ out_ctr,
                    int HW, float stride) {
    __shared__ float xs[8192];       // [ic(256)][px(32)]
    __shared__ float ws[5 * 256];

    const int tid = threadIdx.x;
    for (int i = tid; i < 1280; i += 256) ws[i] = w[i];

    const long p0 = (long)blockIdx.x * 32;
    const int n = (int)(p0 / HW);
    const int s0 = (int)(p0 % HW);
    const float* inN = in + (size_t)n * 256 * HW + s0;
    for (int i = tid; i < 8192; i += 256) {
        int ic = i >> 5, p = i & 31;
        xs[i] = inN[(size_t)ic * HW + p];
    }
    __syncthreads();

    const int px = tid & 31;
    const int g = tid >> 5;
    if (g < 5) {
        float acc = b[g];
        const float* wr = &ws[g * 256];
        for (int ic = 0; ic < 256; ++ic)
            acc = fmaf(xs[(ic << 5) + px], wr[ic], acc);
        const int s = s0 + px;
        if (g == 0)
            out_ctr[(size_t)n * HW + s] = acc;
        else
            out_reg[((size_t)n * 4 + (g - 1)) * HW + s] = fmaxf(acc * stride, 0.f);
    }
}

// ---------------------------------------------------------------------------
// Host launcher
// ---------------------------------------------------------------------------
extern "C" void kernel_launch(void* const* d_in, const int* in_sizes, int n_in,
                              void* d_out, int out_size) {
    (void)in_sizes; (void)n_in; (void)out_size;

    const float* fpn[5];
    for (int i = 0; i < 5; ++i) fpn[i] = (const float*)d_in[i];
    const float* cls_conv_w  = (const float*)d_in[5];
    const float* cls_scale   = (const float*)d_in[6];
    const float* cls_bias    = (const float*)d_in[7];
    const float* cls_final_w = (const float*)d_in[8];
    const float* cls_final_b = (const float*)d_in[9];
    const float* reg_conv_w  = (const float*)d_in[10];
    const float* reg_scale   = (const float*)d_in[11];
    const float* reg_bias    = (const float*)d_in[12];
    const float* reg_final_w = (const float*)d_in[13];
    const float* reg_final_b = (const float*)d_in[14];
    float* out = (float*)d_out;

    float *bufA, *bufB, *wT, *wfc;
    cudaGetSymbolAddress((void**)&bufA, g_bufA);
    cudaGetSymbolAddress((void**)&bufB, g_bufB);
    cudaGetSymbolAddress((void**)&wT,   g_wT);
    cudaGetSymbolAddress((void**)&wfc,  g_wfc);

    const long LAYERW = (long)ICH * 9 * OCH;        // 589824
    const long HEADW  = 4 * LAYERW;
    const long wtot   = 4L * ICH * 9 * OCH;

    transpose_weights<<<(int)((wtot + 255) / 256), 256>>>(cls_conv_w, wT);
    transpose_weights<<<(int)((wtot + 255) / 256), 256>>>(reg_conv_w, wT + HEADW);
    transpose_fc<<<(80 * 256 + 255) / 256, 256>>>(cls_final_w, wfc);

    const int Hs[5] = {128, 64, 32, 16, 8};
    const float strides[5] = {8.f, 16.f, 32.f, 64.f, 128.f};
    long HWs[5], clsOff[5], regOff[5], ctrOff[5];
    for (int l = 0; l < 5; ++l) HWs[l] = (long)Hs[l] * Hs[l];
    long off = 0;
    for (int l = 0; l < 5; ++l) { clsOff[l] = off; off += (long)NB * 80 * HWs[l]; }
    for (int l = 0; l < 5; ++l) { regOff[l] = off; off += (long)NB * 4 * HWs[l]; }
    for (int l = 0; l < 5; ++l) { ctrOff[l] = off; off += (long)NB * 1 * HWs[l]; }

    for (int l = 0; l < 5; ++l) {
        const int H = Hs[l], W = Hs[l];
        const int HW = H * W;
        dim3 grid((H / 8) * (W / 8), OCH / 64, NB);

        for (int head = 0; head < 2; ++head) {
            const float* src = fpn[l];
            const float* wbase = wT + head * HEADW;
            const float* sc = (head == 0) ? cls_scale : reg_scale;
            const float* bi = (head == 0) ? cls_bias : reg_bias;
            for (int i = 0; i < 4; ++i) {
                float* dst = (i & 1) ? bufB : bufA;
                conv3x3_bn_relu<<<grid, 256>>>(src, wbase + i * LAYERW,
                                               sc + i * ICH, bi + i * ICH,
                                               dst, H, W);
                src = dst;
            }
            const int fgrid = NB * HW / 32;
            if (head == 0) {
                final_conv_cls<<<fgrid, 256>>>(src, wfc, cls_final_b,
                                               out + clsOff[l], HW);
            } else {
                final_conv_reg<<<fgrid, 256>>>(src, reg_final_w, reg_final_b,
                                               out + regOff[l], out + ctrOff[l],
                                               HW, strides[l]);
            }
        }
    }
}

// round 10
// speedup vs baseline: 1.1312x; 1.1312x over previous
#include <cuda_runtime.h>
#include <cstdint>

// ---------------------------------------------------------------------------
// FCOS decoder heads, fp32 with packed f32x2 FFMA (Blackwell fma.rn.f32x2).
// 5 FPN levels (128^2..8^2), batch 4, C=256.
// Per head: 4x [conv3x3(256->256) -> BN(scale,bias) -> ReLU], then 1x1 conv.
// cls head -> 80 ch (raw logits + bias)
// reg head -> 5 ch: ch0 = centerness (raw), ch1..4 = max(raw*stride, 0)
// Output order: cls0..4, reg0..4, ctr0..4 (each NCHW, flattened).
// ---------------------------------------------------------------------------

#define ICH 256
#define OCH 256
#define NB  4

// Scratch (no cudaMalloc allowed)
__device__ float g_bufA[(size_t)NB * ICH * 128 * 128];   // 64 MiB
__device__ float g_bufB[(size_t)NB * ICH * 128 * 128];   // 64 MiB
__device__ float g_wT[(size_t)2 * 4 * 9 * ICH * OCH];    // [head][layer][ic][tap][oc]
__device__ float g_wfc[80 * 256];                        // cls final, [ic][oc]

// ---- packed f32x2 helpers --------------------------------------------------
__device__ __forceinline__ unsigned long long f2pk(float x, float y) {
    unsigned long long r;
    asm("mov.b64 %0, {%1, %2};" : "=l"(r) : "f"(x), "f"(y));
    return r;
}
__device__ __forceinline__ void ffma2(unsigned long long& d,
                                      unsigned long long a,
                                      unsigned long long b) {
    asm("fma.rn.f32x2 %0, %1, %2, %0;" : "+l"(d) : "l"(a), "l"(b));
}
__device__ __forceinline__ float2 f2up(unsigned long long v) {
    float2 r;
    asm("mov.b64 {%0, %1}, %2;" : "=f"(r.x), "=f"(r.y) : "l"(v));
    return r;
}

// ---------------------------------------------------------------------------
// Weight transpose: (4, OC, IC, 3, 3) -> (4, IC, 9, OC)
// ---------------------------------------------------------------------------
__global__ void transpose_weights(const float* __restrict__ w,
                                  float* __restrict__ wT) {
    long i = (long)blockIdx.x * blockDim.x + threadIdx.x;
    const long total = 4L * ICH * 9 * OCH;
    if (i >= total) return;
    int oc = (int)(i & (OCH - 1));
    long t = i >> 8;
    int tap = (int)(t % 9); t /= 9;
    int ic = (int)(t & (ICH - 1)); t >>= 8;
    int layer = (int)t;
    wT[i] = w[(((long)(layer * OCH + oc) * ICH + ic) * 9) + tap];
}

// cls final weights: (80, 256) -> (256, 80)
__global__ void transpose_fc(const float* __restrict__ w,
                             float* __restrict__ wT) {
    int i = blockIdx.x * blockDim.x + threadIdx.x;
    if (i >= 80 * 256) return;
    int oc = i % 80;
    int ic = i / 80;
    wT[i] = w[oc * 256 + ic];
}

// ---------------------------------------------------------------------------
// conv3x3 + BN + ReLU.
// Block: 64 output channels x 8x8 spatial tile, 256 threads, 4x4 reg tile.
// wT layout: [ic][tap][oc] (per-layer slice passed in).
// Inner loop uses packed fma.rn.f32x2: accumulators are (oc-pair, px) u64.
// ---------------------------------------------------------------------------
__global__ __launch_bounds__(256)
void conv3x3_bn_relu(const float* __restrict__ in,
                     const float* __restrict__ wT,
                     const float* __restrict__ scale,
                     const float* __restrict__ bias,
                     float* __restrict__ out,
                     int H, int W) {
    __shared__ __align__(16) float sW[16 * 9 * 64];   // [icl][tap][oc64]
    __shared__ __align__(16) float sIn[16 * 100];     // [icl][10][10]

    const int tid = threadIdx.x;
    const int tilesX = W >> 3;
    const int tileX = blockIdx.x % tilesX;
    const int tileY = blockIdx.x / tilesX;
    const int ocb = blockIdx.y << 6;
    const int n = blockIdx.z;
    const int gx0 = tileX << 3;
    const int gy0 = tileY << 3;

    const int ocq = tid >> 4;           // 0..15 (group of 4 oc)
    const int pg  = tid & 15;           // 0..15 (group of 4 px)
    const int row = pg >> 1;            // 0..7
    const int col = (pg & 1) << 2;      // 0 or 4

    // packed accumulators: acc01[j] holds (oc+0, oc+1) for pixel j,
    //                      acc23[j] holds (oc+2, oc+3) for pixel j
    unsigned long long acc01[4], acc23[4];
#pragma unroll
    for (int j = 0; j < 4; ++j) { acc01[j] = 0ull; acc23[j] = 0ull; }

    const float* inN = in + (size_t)n * ICH * H * W;

    for (int ic0 = 0; ic0 < ICH; ic0 += 16) {
        // load input halo tile: 16 x 10 x 10, zero-padded at borders
        for (int i = tid; i < 1600; i += 256) {
            int icl = i / 100;
            int r = i - icl * 100;
            int y = r / 10;
            int x = r - y * 10;
            int gy = gy0 + y - 1;
            int gx = gx0 + x - 1;
            float v = 0.f;
            if ((unsigned)gy < (unsigned)H && (unsigned)gx < (unsigned)W)
                v = inN[((size_t)(ic0 + icl) * H + gy) * W + gx];
            sIn[i] = v;
        }
        // load weights: 16 x 9 x 64, coalesced over oc
        for (int i = tid; i < 9216; i += 256) {
            int icl = i / 576;
            int r = i - icl * 576;
            int tap = r >> 6;
            int oc = r & 63;
            sW[i] = wT[(((size_t)(ic0 + icl) * 9 + tap) << 8) + ocb + oc];
        }
        __syncthreads();

#pragma unroll 2
        for (int icl = 0; icl < 16; ++icl) {
            const float* brow = sIn + icl * 100;
#pragma unroll
            for (int ky = 0; ky < 3; ++ky) {
                const float* bp = brow + (row + ky) * 10 + col;
                // 6-wide b window, each value duplicated into both f32x2 lanes
                unsigned long long bd[6];
#pragma unroll
                for (int m = 0; m < 6; ++m) {
                    float b = bp[m];
                    bd[m] = f2pk(b, b);
                }
#pragma unroll
                for (int kx = 0; kx < 3; ++kx) {
                    const int tap = ky * 3 + kx;
                    // (oc0,oc1) and (oc2,oc3) pairs come pre-packed from SMEM
                    ulonglong2 aw = *(const ulonglong2*)(sW + (icl * 9 + tap) * 64 + (ocq << 2));
#pragma unroll
                    for (int j = 0; j < 4; ++j) {
                        ffma2(acc01[j], aw.x, bd[kx + j]);
                        ffma2(acc23[j], aw.y, bd[kx + j]);
                    }
                }
            }
        }
        __syncthreads();
    }

    // epilogue: BN fold + ReLU
    const size_t HW = (size_t)H * W;
    const size_t base = ((size_t)n * OCH + ocb + (ocq << 2)) * HW;
    const int ocg = ocb + (ocq << 2);
    const float sc0 = scale[ocg + 0], bi0 = bias[ocg + 0];
    const float sc1 = scale[ocg + 1], bi1 = bias[ocg + 1];
    const float sc2 = scale[ocg + 2], bi2 = bias[ocg + 2];
    const float sc3 = scale[ocg + 3], bi3 = bias[ocg + 3];
    const size_t pix = (size_t)(gy0 + row) * W + gx0 + col;
#pragma unroll
    for (int j = 0; j < 4; ++j) {
        float2 v01 = f2up(acc01[j]);
        float2 v23 = f2up(acc23[j]);
        out[base + 0 * HW + pix + j] = fmaxf(fmaf(v01.x, sc0, bi0), 0.f);
        out[base + 1 * HW + pix + j] = fmaxf(fmaf(v01.y, sc1, bi1), 0.f);
        out[base + 2 * HW + pix + j] = fmaxf(fmaf(v23.x, sc2, bi2), 0.f);
        out[base + 3 * HW + pix + j] = fmaxf(fmaf(v23.y, sc3, bi3), 0.f);
    }
}

// ---------------------------------------------------------------------------
// cls final: 1x1 conv 256 -> 80 (+bias). Block: 32 pixels, 8 groups x 10 oc.
// wT layout [ic][80].
// ---------------------------------------------------------------------------
__global__ __launch_bounds__(256)
void final_conv_cls(const float* __restrict__ in,
                    const float* __restrict__ wT,
                    const float* __restrict__ b,
                    float* __restrict__ out, int HW) {
    __shared__ float xs[8192];       // [ic(256)][px(32)]
    __shared__ float ws[32 * 80];    // chunk of 32 ic x 80 oc

    const int tid = threadIdx.x;
    const long p0 = (long)blockIdx.x * 32;
    const int n = (int)(p0 / HW);
    const int s0 = (int)(p0 % HW);
    const float* inN = in + (size_t)n * 256 * HW + s0;

    for (int i = tid; i < 8192; i += 256) {
        int ic = i >> 5, p = i & 31;
        xs[i] = inN[(size_t)ic * HW + p];
    }

    const int px = tid & 31;
    const int g = tid >> 5;
    const int oc0 = g * 10;
    float acc[10];
#pragma unroll
    for (int j = 0; j < 10; ++j) acc[j] = b[oc0 + j];

    for (int ic0 = 0; ic0 < 256; ic0 += 32) {
        __syncthreads();
        for (int i = tid; i < 2560; i += 256) ws[i] = wT[ic0 * 80 + i];
        __syncthreads();
        for (int icc = 0; icc < 32; ++icc) {
            float x = xs[((ic0 + icc) << 5) + px];
            const float* wr = &ws[icc * 80 + oc0];
#pragma unroll
            for (int j = 0; j < 10; ++j) acc[j] = fmaf(x, wr[j], acc[j]);
        }
    }

    const int s = s0 + px;
#pragma unroll
    for (int j = 0; j < 10; ++j)
        out[((size_t)n * 80 + oc0 + j) * HW + s] = acc[j];
}

// ---------------------------------------------------------------------------
// reg final: 1x1 conv 256 -> 5 (+bias). ch0 -> centerness (raw),
// ch1..4 -> max(raw * stride, 0). w layout [oc(5)][ic(256)].
// ---------------------------------------------------------------------------
__global__ __launch_bounds__(256)
void final_conv_reg(const float* __restrict__ in,
                    const float* __restrict__ w,
                    const float* __restrict__ b,
                    float* __restrict__ out_reg,
                    float* __restrict__ out_ctr,
                    int HW, float stride) {
    __shared__ float xs[8192];       // [ic(256)][px(32)]
    __shared__ float ws[5 * 256];

    const int tid = threadIdx.x;
    for (int i = tid; i < 1280; i += 256) ws[i] = w[i];

    const long p0 = (long)blockIdx.x * 32;
    const int n = (int)(p0 / HW);
    const int s0 = (int)(p0 % HW);
    const float* inN = in + (size_t)n * 256 * HW + s0;
    for (int i = tid; i < 8192; i += 256) {
        int ic = i >> 5, p = i & 31;
        xs[i] = inN[(size_t)ic * HW + p];
    }
    __syncthreads();

    const int px = tid & 31;
    const int g = tid >> 5;
    if (g < 5) {
        float acc = b[g];
        const float* wr = &ws[g * 256];
        for (int ic = 0; ic < 256; ++ic)
            acc = fmaf(xs[(ic << 5) + px], wr[ic], acc);
        const int s = s0 + px;
        if (g == 0)
            out_ctr[(size_t)n * HW + s] = acc;
        else
            out_reg[((size_t)n * 4 + (g - 1)) * HW + s] = fmaxf(acc * stride, 0.f);
    }
}

// ---------------------------------------------------------------------------
// Host launcher
// ---------------------------------------------------------------------------
extern "C" void kernel_launch(void* const* d_in, const int* in_sizes, int n_in,
                              void* d_out, int out_size) {
    (void)in_sizes; (void)n_in; (void)out_size;

    const float* fpn[5];
    for (int i = 0; i < 5; ++i) fpn[i] = (const float*)d_in[i];
    const float* cls_conv_w  = (const float*)d_in[5];
    const float* cls_scale   = (const float*)d_in[6];
    const float* cls_bias    = (const float*)d_in[7];
    const float* cls_final_w = (const float*)d_in[8];
    const float* cls_final_b = (const float*)d_in[9];
    const float* reg_conv_w  = (const float*)d_in[10];
    const float* reg_scale   = (const float*)d_in[11];
    const float* reg_bias    = (const float*)d_in[12];
    const float* reg_final_w = (const float*)d_in[13];
    const float* reg_final_b = (const float*)d_in[14];
    float* out = (float*)d_out;

    float *bufA, *bufB, *wT, *wfc;
    cudaGetSymbolAddress((void**)&bufA, g_bufA);
    cudaGetSymbolAddress((void**)&bufB, g_bufB);
    cudaGetSymbolAddress((void**)&wT,   g_wT);
    cudaGetSymbolAddress((void**)&wfc,  g_wfc);

    const long LAYERW = (long)ICH * 9 * OCH;        // 589824
    const long HEADW  = 4 * LAYERW;
    const long wtot   = 4L * ICH * 9 * OCH;

    transpose_weights<<<(int)((wtot + 255) / 256), 256>>>(cls_conv_w, wT);
    transpose_weights<<<(int)((wtot + 255) / 256), 256>>>(reg_conv_w, wT + HEADW);
    transpose_fc<<<(80 * 256 + 255) / 256, 256>>>(cls_final_w, wfc);

    const int Hs[5] = {128, 64, 32, 16, 8};
    const float strides[5] = {8.f, 16.f, 32.f, 64.f, 128.f};
    long HWs[5], clsOff[5], regOff[5], ctrOff[5];
    for (int l = 0; l < 5; ++l) HWs[l] = (long)Hs[l] * Hs[l];
    long off = 0;
    for (int l = 0; l < 5; ++l) { clsOff[l] = off; off += (long)NB * 80 * HWs[l]; }
    for (int l = 0; l < 5; ++l) { regOff[l] = off; off += (long)NB * 4 * HWs[l]; }
    for (int l = 0; l < 5; ++l) { ctrOff[l] = off; off += (long)NB * 1 * HWs[l]; }

    for (int l = 0; l < 5; ++l) {
        const int H = Hs[l], W = Hs[l];
        const int HW = H * W;
        dim3 grid((H / 8) * (W / 8), OCH / 64, NB);

        for (int head = 0; head < 2; ++head) {
            const float* src = fpn[l];
            const float* wbase = wT + head * HEADW;
            const float* sc = (head == 0) ? cls_scale : reg_scale;
            const float* bi = (head == 0) ? cls_bias : reg_bias;
            for (int i = 0; i < 4; ++i) {
                float* dst = (i & 1) ? bufB : bufA;
                conv3x3_bn_relu<<<grid, 256>>>(src, wbase + i * LAYERW,
                                               sc + i * ICH, bi + i * ICH,
                                               dst, H, W);
                src = dst;
            }
            const int fgrid = NB * HW / 32;
            if (head == 0) {
                final_conv_cls<<<fgrid, 256>>>(src, wfc, cls_final_b,
                                               out + clsOff[l], HW);
            } else {
                final_conv_reg<<<fgrid, 256>>>(src, reg_final_w, reg_final_b,
                                               out + regOff[l], out + ctrOff[l],
                                               HW, strides[l]);
            }
        }
    }
}

// round 11
// speedup vs baseline: 1.2121x; 1.0715x over previous
#include <cuda_runtime.h>
#include <cstdint>

// ---------------------------------------------------------------------------
// FCOS decoder heads, fp32 with packed f32x2 FFMA (Blackwell fma.rn.f32x2).
// Conv tile rebalanced: 128 threads/block, thread = 4 oc x 8 px (full row)
// to cut shared-memory bytes per FMA (L1 was 91% -> binding pipe).
// ---------------------------------------------------------------------------

#define ICH 256
#define OCH 256
#define NB  4

// Scratch (no cudaMalloc allowed)
__device__ float g_bufA[(size_t)NB * ICH * 128 * 128];   // 64 MiB
__device__ float g_bufB[(size_t)NB * ICH * 128 * 128];   // 64 MiB
__device__ float g_wT[(size_t)2 * 4 * 9 * ICH * OCH];    // [head][layer][ic][tap][oc]
__device__ float g_wfc[80 * 256];                        // cls final, [ic][oc]

// ---- packed f32x2 helpers --------------------------------------------------
__device__ __forceinline__ unsigned long long f2pk(float x, float y) {
    unsigned long long r;
    asm("mov.b64 %0, {%1, %2};" : "=l"(r) : "f"(x), "f"(y));
    return r;
}
__device__ __forceinline__ void ffma2(unsigned long long& d,
                                      unsigned long long a,
                                      unsigned long long b) {
    asm("fma.rn.f32x2 %0, %1, %2, %0;" : "+l"(d) : "l"(a), "l"(b));
}
__device__ __forceinline__ float2 f2up(unsigned long long v) {
    float2 r;
    asm("mov.b64 {%0, %1}, %2;" : "=f"(r.x), "=f"(r.y) : "l"(v));
    return r;
}

// ---------------------------------------------------------------------------
// Weight transpose: (4, OC, IC, 3, 3) -> (4, IC, 9, OC)
// ---------------------------------------------------------------------------
__global__ void transpose_weights(const float* __restrict__ w,
                                  float* __restrict__ wT) {
    long i = (long)blockIdx.x * blockDim.x + threadIdx.x;
    const long total = 4L * ICH * 9 * OCH;
    if (i >= total) return;
    int oc = (int)(i & (OCH - 1));
    long t = i >> 8;
    int tap = (int)(t % 9); t /= 9;
    int ic = (int)(t & (ICH - 1)); t >>= 8;
    int layer = (int)t;
    wT[i] = w[(((long)(layer * OCH + oc) * ICH + ic) * 9) + tap];
}

// cls final weights: (80, 256) -> (256, 80)
__global__ void transpose_fc(const float* __restrict__ w,
                             float* __restrict__ wT) {
    int i = blockIdx.x * blockDim.x + threadIdx.x;
    if (i >= 80 * 256) return;
    int oc = i % 80;
    int ic = i / 80;
    wT[i] = w[oc * 256 + ic];
}

// ---------------------------------------------------------------------------
// conv3x3 + BN + ReLU.
// Block: 128 threads, tile = 64 oc x 8x8 px. Thread: 4 oc x 8 px (one row).
// ocq = tid>>3 (16 groups of 4 oc), row = tid&7.
// wT layout: [ic][tap][oc]. Packed f32x2 over oc pairs.
// ---------------------------------------------------------------------------
__global__ __launch_bounds__(128)
void conv3x3_bn_relu(const float* __restrict__ in,
                     const float* __restrict__ wT,
                     const float* __restrict__ scale,
                     const float* __restrict__ bias,
                     float* __restrict__ out,
                     int H, int W) {
    __shared__ __align__(16) float sW[16 * 9 * 64];   // [icl][tap][oc64]
    __shared__ __align__(16) float sIn[16 * 100];     // [icl][10][10]

    const int tid = threadIdx.x;
    const int tilesX = W >> 3;
    const int tileX = blockIdx.x % tilesX;
    const int tileY = blockIdx.x / tilesX;
    const int ocb = blockIdx.y << 6;
    const int n = blockIdx.z;
    const int gx0 = tileX << 3;
    const int gy0 = tileY << 3;

    const int ocq = tid >> 3;           // 0..15 (group of 4 oc)
    const int row = tid & 7;            // 0..7 (output row)

    // packed accumulators: acc01[j] = (oc+0, oc+1) px j ; acc23[j] = (oc+2, oc+3)
    unsigned long long acc01[8], acc23[8];
#pragma unroll
    for (int j = 0; j < 8; ++j) { acc01[j] = 0ull; acc23[j] = 0ull; }

    const float* inN = in + (size_t)n * ICH * H * W;

    for (int ic0 = 0; ic0 < ICH; ic0 += 16) {
        // load input halo tile: 16 x 10 x 10, zero-padded at borders
        for (int i = tid; i < 1600; i += 128) {
            int icl = i / 100;
            int r = i - icl * 100;
            int y = r / 10;
            int x = r - y * 10;
            int gy = gy0 + y - 1;
            int gx = gx0 + x - 1;
            float v = 0.f;
            if ((unsigned)gy < (unsigned)H && (unsigned)gx < (unsigned)W)
                v = inN[((size_t)(ic0 + icl) * H + gy) * W + gx];
            sIn[i] = v;
        }
        // load weights: 16 x 9 x 64, coalesced over oc
        for (int i = tid; i < 9216; i += 128) {
            int icl = i / 576;
            int r = i - icl * 576;
            int tap = r >> 6;
            int oc = r & 63;
            sW[i] = wT[(((size_t)(ic0 + icl) * 9 + tap) << 8) + ocb + oc];
        }
        __syncthreads();

#pragma unroll 2
        for (int icl = 0; icl < 16; ++icl) {
            const float* brow = sIn + icl * 100;
#pragma unroll
            for (int ky = 0; ky < 3; ++ky) {
                const float* bp = brow + (row + ky) * 10;
                // 10-wide b window, each value duplicated into both f32x2 lanes
                unsigned long long bd[10];
#pragma unroll
                for (int m = 0; m < 10; ++m) {
                    float b = bp[m];
                    bd[m] = f2pk(b, b);
                }
#pragma unroll
                for (int kx = 0; kx < 3; ++kx) {
                    const int tap = ky * 3 + kx;
                    // (oc0,oc1),(oc2,oc3) come pre-packed from SMEM
                    ulonglong2 aw = *(const ulonglong2*)(sW + (icl * 9 + tap) * 64 + (ocq << 2));
#pragma unroll
                    for (int j = 0; j < 8; ++j) {
                        ffma2(acc01[j], aw.x, bd[kx + j]);
                        ffma2(acc23[j], aw.y, bd[kx + j]);
                    }
                }
            }
        }
        __syncthreads();
    }

    // epilogue: BN fold + ReLU, vectorized float4 stores (8 px per row)
    const size_t HW = (size_t)H * W;
    const int ocg = ocb + (ocq << 2);
    const size_t base = ((size_t)n * OCH + ocg) * HW;
    const size_t pix = (size_t)(gy0 + row) * W + gx0;
    const float sc0 = scale[ocg + 0], bi0 = bias[ocg + 0];
    const float sc1 = scale[ocg + 1], bi1 = bias[ocg + 1];
    const float sc2 = scale[ocg + 2], bi2 = bias[ocg + 2];
    const float sc3 = scale[ocg + 3], bi3 = bias[ocg + 3];

    float r0[8], r1[8], r2[8], r3[8];
#pragma unroll
    for (int j = 0; j < 8; ++j) {
        float2 v01 = f2up(acc01[j]);
        float2 v23 = f2up(acc23[j]);
        r0[j] = fmaxf(fmaf(v01.x, sc0, bi0), 0.f);
        r1[j] = fmaxf(fmaf(v01.y, sc1, bi1), 0.f);
        r2[j] = fmaxf(fmaf(v23.x, sc2, bi2), 0.f);
        r3[j] = fmaxf(fmaf(v23.y, sc3, bi3), 0.f);
    }
    float* o0 = out + base + 0 * HW + pix;
    float* o1 = out + base + 1 * HW + pix;
    float* o2 = out + base + 2 * HW + pix;
    float* o3 = out + base + 3 * HW + pix;
    *(float4*)(o0 + 0) = make_float4(r0[0], r0[1], r0[2], r0[3]);
    *(float4*)(o0 + 4) = make_float4(r0[4], r0[5], r0[6], r0[7]);
    *(float4*)(o1 + 0) = make_float4(r1[0], r1[1], r1[2], r1[3]);
    *(float4*)(o1 + 4) = make_float4(r1[4], r1[5], r1[6], r1[7]);
    *(float4*)(o2 + 0) = make_float4(r2[0], r2[1], r2[2], r2[3]);
    *(float4*)(o2 + 4) = make_float4(r2[4], r2[5], r2[6], r2[7]);
    *(float4*)(o3 + 0) = make_float4(r3[0], r3[1], r3[2], r3[3]);
    *(float4*)(o3 + 4) = make_float4(r3[4], r3[5], r3[6], r3[7]);
}

// ---------------------------------------------------------------------------
// cls final: 1x1 conv 256 -> 80 (+bias). Block: 32 pixels, 8 groups x 10 oc.
// wT layout [ic][80].
// ---------------------------------------------------------------------------
__global__ __launch_bounds__(256)
void final_conv_cls(const float* __restrict__ in,
                    const float* __restrict__ wT,
                    const float* __restrict__ b,
                    float* __restrict__ out, int HW) {
    __shared__ float xs[8192];       // [ic(256)][px(32)]
    __shared__ float ws[32 * 80];    // chunk of 32 ic x 80 oc

    const int tid = threadIdx.x;
    const long p0 = (long)blockIdx.x * 32;
    const int n = (int)(p0 / HW);
    const int s0 = (int)(p0 % HW);
    const float* inN = in + (size_t)n * 256 * HW + s0;

    for (int i = tid; i < 8192; i += 256) {
        int ic = i >> 5, p = i & 31;
        xs[i] = inN[(size_t)ic * HW + p];
    }

    const int px = tid & 31;
    const int g = tid >> 5;
    const int oc0 = g * 10;
    float acc[10];
#pragma unroll
    for (int j = 0; j < 10; ++j) acc[j] = b[oc0 + j];

    for (int ic0 = 0; ic0 < 256; ic0 += 32) {
        __syncthreads();
        for (int i = tid; i < 2560; i += 256) ws[i] = wT[ic0 * 80 + i];
        __syncthreads();
        for (int icc = 0; icc < 32; ++icc) {
            float x = xs[((ic0 + icc) << 5) + px];
            const float* wr = &ws[icc * 80 + oc0];
#pragma unroll
            for (int j = 0; j < 10; ++j) acc[j] = fmaf(x, wr[j], acc[j]);
        }
    }

    const int s = s0 + px;
#pragma unroll
    for (int j = 0; j < 10; ++j)
        out[((size_t)n * 80 + oc0 + j) * HW + s] = acc[j];
}

// ---------------------------------------------------------------------------
// reg final: 1x1 conv 256 -> 5 (+bias). ch0 -> centerness (raw),
// ch1..4 -> max(raw * stride, 0). w layout [oc(5)][ic(256)].
// ---------------------------------------------------------------------------
__global__ __launch_bounds__(256)
void final_conv_reg(const float* __restrict__ in,
                    const float* __restrict__ w,
                    const float* __restrict__ b,
                    float* __restrict__ out_reg,
                    float* __restrict__ out_ctr,
                    int HW, float stride) {
    __shared__ float xs[8192];       // [ic(256)][px(32)]
    __shared__ float ws[5 * 256];

    const int tid = threadIdx.x;
    for (int i = tid; i < 1280; i += 256) ws[i] = w[i];

    const long p0 = (long)blockIdx.x * 32;
    const int n = (int)(p0 / HW);
    const int s0 = (int)(p0 % HW);
    const float* inN = in + (size_t)n * 256 * HW + s0;
    for (int i = tid; i < 8192; i += 256) {
        int ic = i >> 5, p = i & 31;
        xs[i] = inN[(size_t)ic * HW + p];
    }
    __syncthreads();

    const int px = tid & 31;
    const int g = tid >> 5;
    if (g < 5) {
        float acc = b[g];
        const float* wr = &ws[g * 256];
        for (int ic = 0; ic < 256; ++ic)
            acc = fmaf(xs[(ic << 5) + px], wr[ic], acc);
        const int s = s0 + px;
        if (g == 0)
            out_ctr[(size_t)n * HW + s] = acc;
        else
            out_reg[((size_t)n * 4 + (g - 1)) * HW + s] = fmaxf(acc * stride, 0.f);
    }
}

// ---------------------------------------------------------------------------
// Host launcher
// ---------------------------------------------------------------------------
extern "C" void kernel_launch(void* const* d_in, const int* in_sizes, int n_in,
                              void* d_out, int out_size) {
    (void)in_sizes; (void)n_in; (void)out_size;

    const float* fpn[5];
    for (int i = 0; i < 5; ++i) fpn[i] = (const float*)d_in[i];
    const float* cls_conv_w  = (const float*)d_in[5];
    const float* cls_scale   = (const float*)d_in[6];
    const float* cls_bias    = (const float*)d_in[7];
    const float* cls_final_w = (const float*)d_in[8];
    const float* cls_final_b = (const float*)d_in[9];
    const float* reg_conv_w  = (const float*)d_in[10];
    const float* reg_scale   = (const float*)d_in[11];
    const float* reg_bias    = (const float*)d_in[12];
    const float* reg_final_w = (const float*)d_in[13];
    const float* reg_final_b = (const float*)d_in[14];
    float* out = (float*)d_out;

    float *bufA, *bufB, *wT, *wfc;
    cudaGetSymbolAddress((void**)&bufA, g_bufA);
    cudaGetSymbolAddress((void**)&bufB, g_bufB);
    cudaGetSymbolAddress((void**)&wT,   g_wT);
    cudaGetSymbolAddress((void**)&wfc,  g_wfc);

    const long LAYERW = (long)ICH * 9 * OCH;        // 589824
    const long HEADW  = 4 * LAYERW;
    const long wtot   = 4L * ICH * 9 * OCH;

    transpose_weights<<<(int)((wtot + 255) / 256), 256>>>(cls_conv_w, wT);
    transpose_weights<<<(int)((wtot + 255) / 256), 256>>>(reg_conv_w, wT + HEADW);
    transpose_fc<<<(80 * 256 + 255) / 256, 256>>>(cls_final_w, wfc);

    const int Hs[5] = {128, 64, 32, 16, 8};
    const float strides[5] = {8.f, 16.f, 32.f, 64.f, 128.f};
    long HWs[5], clsOff[5], regOff[5], ctrOff[5];
    for (int l = 0; l < 5; ++l) HWs[l] = (long)Hs[l] * Hs[l];
    long off = 0;
    for (int l = 0; l < 5; ++l) { clsOff[l] = off; off += (long)NB * 80 * HWs[l]; }
    for (int l = 0; l < 5; ++l) { regOff[l] = off; off += (long)NB * 4 * HWs[l]; }
    for (int l = 0; l < 5; ++l) { ctrOff[l] = off; off += (long)NB * 1 * HWs[l]; }

    for (int l = 0; l < 5; ++l) {
        const int H = Hs[l], W = Hs[l];
        const int HW = H * W;
        dim3 grid((H / 8) * (W / 8), OCH / 64, NB);

        for (int head = 0; head < 2; ++head) {
            const float* src = fpn[l];
            const float* wbase = wT + head * HEADW;
            const float* sc = (head == 0) ? cls_scale : reg_scale;
            const float* bi = (head == 0) ? cls_bias : reg_bias;
            for (int i = 0; i < 4; ++i) {
                float* dst = (i & 1) ? bufB : bufA;
                conv3x3_bn_relu<<<grid, 128>>>(src, wbase + i * LAYERW,
                                               sc + i * ICH, bi + i * ICH,
                                               dst, H, W);
                src = dst;
            }
            const int fgrid = NB * HW / 32;
            if (head == 0) {
                final_conv_cls<<<fgrid, 256>>>(src, wfc, cls_final_b,
                                               out + clsOff[l], HW);
            } else {
                final_conv_reg<<<fgrid, 256>>>(src, reg_final_w, reg_final_b,
                                               out + regOff[l], out + ctrOff[l],
                                               HW, strides[l]);
            }
        }
    }
}

// round 12
// speedup vs baseline: 1.4012x; 1.1560x over previous
#include <cuda_runtime.h>
#include <cuda_bf16.h>
#include <cstdint>

// ---------------------------------------------------------------------------
// FCOS decoder heads. Conv3x3 layers on tensor cores (mma.sync.m16n8k16.bf16)
// with 3-term hi/lo bf16 split for fp32-grade accuracy:
//   W*X ~= Wh*Xh + Wl*Xh + Wh*Xl   (residual ~2^-17)
// Block: 128 threads / 4 warps; tile 64 oc x 64 px (8x8); K = 256 ic x 9 taps.
// Output order: cls0..4, reg0..4, ctr0..4 (each NCHW, flattened).
// ---------------------------------------------------------------------------

#define ICH 256
#define OCH 256
#define NB  4

// Scratch (no cudaMalloc allowed)
__device__ float g_bufA[(size_t)NB * ICH * 128 * 128];   // 64 MiB
__device__ float g_bufB[(size_t)NB * ICH * 128 * 128];   // 64 MiB
// packed bf16-pair words: [head][layer][chunk16][h(hi/lo)][tap9][oc256][w8]
__device__ uint32_t g_wb[(size_t)2 * 4 * 16 * 2 * 9 * 256 * 8];
__device__ float g_wfc[80 * 256];                        // cls final, [ic][oc]

// ---- helpers ---------------------------------------------------------------
__device__ __forceinline__ uint32_t packbf(__nv_bfloat16 a, __nv_bfloat16 b) {
    __nv_bfloat162 t(a, b);                 // .x = a (low), .y = b (high)
    return *reinterpret_cast<uint32_t*>(&t);
}

__device__ __forceinline__ void mma16816(float* d, const uint32_t* a,
                                         const uint32_t* b) {
    asm volatile(
        "mma.sync.aligned.m16n8k16.row.col.f32.bf16.bf16.f32 "
        "{%0,%1,%2,%3},{%4,%5,%6,%7},{%8,%9},{%0,%1,%2,%3};"
        : "+f"(d[0]), "+f"(d[1]), "+f"(d[2]), "+f"(d[3])
        : "r"(a[0]), "r"(a[1]), "r"(a[2]), "r"(a[3]), "r"(b[0]), "r"(b[1]));
}

// ---------------------------------------------------------------------------
// Weight split/pack: fp32 (4, OC, IC, 3, 3) ->
//   words [(layer,chunk,h,tap,oc,w)] ; word = bf16(ic=2w) | bf16(ic=2w+1)<<16
// ---------------------------------------------------------------------------
__global__ void wsplit(const float* __restrict__ w, uint32_t* __restrict__ out) {
    long i = (long)blockIdx.x * blockDim.x + threadIdx.x;
    const long total = 4L * 16 * 2 * 9 * 256 * 8;
    if (i >= total) return;
    int wd = (int)(i & 7);
    long t = i >> 3;
    int oc = (int)(t & 255); t >>= 8;
    int tap = (int)(t % 9); t /= 9;
    int h = (int)(t & 1); t >>= 1;
    int chunk = (int)(t & 15); t >>= 4;
    int layer = (int)t;
    int ic0 = chunk * 16 + wd * 2;
    float v0 = w[(((long)(layer * 256 + oc) * 256 + ic0) * 9) + tap];
    float v1 = w[(((long)(layer * 256 + oc) * 256 + ic0 + 1) * 9) + tap];
    __nv_bfloat16 h0 = __float2bfloat16_rn(v0);
    __nv_bfloat16 h1 = __float2bfloat16_rn(v1);
    if (h == 0) {
        out[i] = packbf(h0, h1);
    } else {
        __nv_bfloat16 l0 = __float2bfloat16_rn(v0 - __bfloat162float(h0));
        __nv_bfloat16 l1 = __float2bfloat16_rn(v1 - __bfloat162float(h1));
        out[i] = packbf(l0, l1);
    }
}

// cls final weights: (80, 256) -> (256, 80)
__global__ void transpose_fc(const float* __restrict__ w,
                             float* __restrict__ wT) {
    int i = blockIdx.x * blockDim.x + threadIdx.x;
    if (i >= 80 * 256) return;
    int oc = i % 80;
    int ic = i / 80;
    wT[i] = w[oc * 256 + ic];
}

// ---------------------------------------------------------------------------
// conv3x3 + BN + ReLU via tensor cores.
// 128 threads, 4 warps: warp_m = wid&1 (2 x 16oc tiles), warp_n = wid>>1
// (4 rows of 8 px each). Smem rows padded to 12 words (conflict-free).
// sW: [h2][tap9][oc64][12w], sX: [h2][y10][x10][12w]
// ---------------------------------------------------------------------------
#define SW_WORDS (2 * 9 * 64 * 12)   // 13824
#define SX_WORDS (2 * 10 * 10 * 12)  // 2400
#define SMEM_BYTES ((SW_WORDS + SX_WORDS) * 4)   // 64896

__global__ __launch_bounds__(128)
void conv3x3_mma(const float* __restrict__ in,
                 const uint32_t* __restrict__ wb,   // per-layer base
                 const float* __restrict__ scale,
                 const float* __restrict__ bias,
                 float* __restrict__ out,
                 int H, int W) {
    extern __shared__ uint32_t sm[];
    uint32_t* sW = sm;               // h-stride 9*64*12 = 6912
    uint32_t* sX = sm + SW_WORDS;    // h-stride 100*12 = 1200

    const int tid = threadIdx.x;
    const int lane = tid & 31;
    const int wid = tid >> 5;
    const int warp_m = wid & 1;
    const int warp_n = wid >> 1;
    const int lq = lane >> 2;   // 0..7
    const int lr = lane & 3;    // 0..3

    const int tilesX = W >> 3;
    const int tileX = blockIdx.x % tilesX;
    const int tileY = blockIdx.x / tilesX;
    const int ocb = blockIdx.y << 6;
    const int n = blockIdx.z;
    const int gx0 = tileX << 3;
    const int gy0 = tileY << 3;
    const int HW = H * W;

    const float* inN = in + (size_t)n * ICH * HW;

    float acc[2][4][4];
#pragma unroll
    for (int mi = 0; mi < 2; ++mi)
#pragma unroll
        for (int ni = 0; ni < 4; ++ni)
#pragma unroll
            for (int k = 0; k < 4; ++k) acc[mi][ni][k] = 0.f;

    for (int chunk = 0; chunk < 16; ++chunk) {
        const int ic0 = chunk << 4;
        // ---- weight fill: 2*9*64*8 = 9216 words, coalesced ----
        const uint32_t* wsrc = wb + (size_t)chunk * (2 * 9 * 256 * 8);
        for (int i = tid; i < 9216; i += 128) {
            int wd = i & 7;
            int t = i >> 3;
            int oc = t & 63; t >>= 6;        // t: 0..17
            int tap = t % 9;
            int h = t / 9;
            sW[((h * 9 + tap) * 64 + oc) * 12 + wd] =
                wsrc[((size_t)(h * 9 + tap) * 256 + ocb + oc) * 8 + wd];
        }
        // ---- halo fill: 10x10 px, 8 ic-pair words, hi+lo ----
        for (int i = tid; i < 800; i += 128) {
            int y = i / 80;
            int r = i % 80;
            int wd = r / 10;
            int x = r % 10;
            int gy = gy0 + y - 1;
            int gx = gx0 + x - 1;
            float v0 = 0.f, v1 = 0.f;
            if ((unsigned)gy < (unsigned)H && (unsigned)gx < (unsigned)W) {
                const float* p = inN + (size_t)(ic0 + 2 * wd) * HW + gy * W + gx;
                v0 = p[0];
                v1 = p[HW];
            }
            __nv_bfloat16 h0 = __float2bfloat16_rn(v0);
            __nv_bfloat16 h1 = __float2bfloat16_rn(v1);
            __nv_bfloat16 l0 = __float2bfloat16_rn(v0 - __bfloat162float(h0));
            __nv_bfloat16 l1 = __float2bfloat16_rn(v1 - __bfloat162float(h1));
            sX[((0 * 10 + y) * 10 + x) * 12 + wd] = packbf(h0, h1);
            sX[((1 * 10 + y) * 10 + x) * 12 + wd] = packbf(l0, l1);
        }
        __syncthreads();

#pragma unroll
        for (int tap = 0; tap < 9; ++tap) {
            const int dy = tap / 3, dx = tap % 3;
            // A fragments (hi, lo) for 2 m-tiles
            uint32_t ah[2][4], al[2][4];
#pragma unroll
            for (int mi = 0; mi < 2; ++mi) {
                const int ocr = warp_m * 32 + mi * 16;
                const uint32_t* pw = sW + (tap * 64 + ocr) * 12;
                ah[mi][0] = pw[lq * 12 + lr];
                ah[mi][1] = pw[(lq + 8) * 12 + lr];
                ah[mi][2] = pw[lq * 12 + lr + 4];
                ah[mi][3] = pw[(lq + 8) * 12 + lr + 4];
                const uint32_t* pl = pw + 6912;   // h=1
                al[mi][0] = pl[lq * 12 + lr];
                al[mi][1] = pl[(lq + 8) * 12 + lr];
                al[mi][2] = pl[lq * 12 + lr + 4];
                al[mi][3] = pl[(lq + 8) * 12 + lr + 4];
            }
            // B fragments (hi, lo) for 4 n-tiles (rows)
            uint32_t bh[4][2], bl[4][2];
#pragma unroll
            for (int ni = 0; ni < 4; ++ni) {
                const int y = warp_n * 4 + ni + dy;
                const int x = lq + dx;
                const uint32_t* px_ = sX + (y * 10 + x) * 12;
                bh[ni][0] = px_[lr];
                bh[ni][1] = px_[lr + 4];
                bl[ni][0] = px_[1200 + lr];
                bl[ni][1] = px_[1200 + lr + 4];
            }
#pragma unroll
            for (int mi = 0; mi < 2; ++mi)
#pragma unroll
                for (int ni = 0; ni < 4; ++ni) {
                    mma16816(acc[mi][ni], ah[mi], bh[ni]);
                    mma16816(acc[mi][ni], al[mi], bh[ni]);
                    mma16816(acc[mi][ni], ah[mi], bl[ni]);
                }
        }
        __syncthreads();
    }

    // ---- epilogue: BN fold + ReLU ----
#pragma unroll
    for (int mi = 0; mi < 2; ++mi) {
        const int oc0 = ocb + warp_m * 32 + mi * 16 + lq;
        const int oc1 = oc0 + 8;
        const float s0 = scale[oc0], b0 = bias[oc0];
        const float s1 = scale[oc1], b1 = bias[oc1];
        float* o0 = out + ((size_t)n * OCH + oc0) * HW;
        float* o1 = out + ((size_t)n * OCH + oc1) * HW;
#pragma unroll
        for (int ni = 0; ni < 4; ++ni) {
            const int py = warp_n * 4 + ni;
            const size_t pix = (size_t)(gy0 + py) * W + gx0 + lr * 2;
            float2 v0, v1;
            v0.x = fmaxf(fmaf(acc[mi][ni][0], s0, b0), 0.f);
            v0.y = fmaxf(fmaf(acc[mi][ni][1], s0, b0), 0.f);
            v1.x = fmaxf(fmaf(acc[mi][ni][2], s1, b1), 0.f);
            v1.y = fmaxf(fmaf(acc[mi][ni][3], s1, b1), 0.f);
            *(float2*)(o0 + pix) = v0;
            *(float2*)(o1 + pix) = v1;
        }
    }
}

// ---------------------------------------------------------------------------
// cls final: 1x1 conv 256 -> 80 (+bias). Block: 32 pixels, 8 groups x 10 oc.
// ---------------------------------------------------------------------------
__global__ __launch_bounds__(256)
void final_conv_cls(const float* __restrict__ in,
                    const float* __restrict__ wT,
                    const float* __restrict__ b,
                    float* __restrict__ out, int HW) {
    __shared__ float xs[8192];       // [ic(256)][px(32)]
    __shared__ float ws[32 * 80];

    const int tid = threadIdx.x;
    const long p0 = (long)blockIdx.x * 32;
    const int n = (int)(p0 / HW);
    const int s0 = (int)(p0 % HW);
    const float* inN = in + (size_t)n * 256 * HW + s0;

    for (int i = tid; i < 8192; i += 256) {
        int ic = i >> 5, p = i & 31;
        xs[i] = inN[(size_t)ic * HW + p];
    }

    const int px = tid & 31;
    const int g = tid >> 5;
    const int oc0 = g * 10;
    float acc[10];
#pragma unroll
    for (int j = 0; j < 10; ++j) acc[j] = b[oc0 + j];

    for (int ic0 = 0; ic0 < 256; ic0 += 32) {
        __syncthreads();
        for (int i = tid; i < 2560; i += 256) ws[i] = wT[ic0 * 80 + i];
        __syncthreads();
        for (int icc = 0; icc < 32; ++icc) {
            float x = xs[((ic0 + icc) << 5) + px];
            const float* wr = &ws[icc * 80 + oc0];
#pragma unroll
            for (int j = 0; j < 10; ++j) acc[j] = fmaf(x, wr[j], acc[j]);
        }
    }

    const int s = s0 + px;
#pragma unroll
    for (int j = 0; j < 10; ++j)
        out[((size_t)n * 80 + oc0 + j) * HW + s] = acc[j];
}

// ---------------------------------------------------------------------------
// reg final: 1x1 conv 256 -> 5 (+bias). ch0 -> centerness (raw),
// ch1..4 -> max(raw * stride, 0). w layout [oc(5)][ic(256)].
// ---------------------------------------------------------------------------
__global__ __launch_bounds__(256)
void final_conv_reg(const float* __restrict__ in,
                    const float* __restrict__ w,
                    const float* __restrict__ b,
                    float* __restrict__ out_reg,
                    float* __restrict__ out_ctr,
                    int HW, float stride) {
    __shared__ float xs[8192];
    __shared__ float ws[5 * 256];

    const int tid = threadIdx.x;
    for (int i = tid; i < 1280; i += 256) ws[i] = w[i];

    const long p0 = (long)blockIdx.x * 32;
    const int n = (int)(p0 / HW);
    const int s0 = (int)(p0 % HW);
    const float* inN = in + (size_t)n * 256 * HW + s0;
    for (int i = tid; i < 8192; i += 256) {
        int ic = i >> 5, p = i & 31;
        xs[i] = inN[(size_t)ic * HW + p];
    }
    __syncthreads();

    const int px = tid & 31;
    const int g = tid >> 5;
    if (g < 5) {
        float acc = b[g];
        const float* wr = &ws[g * 256];
        for (int ic = 0; ic < 256; ++ic)
            acc = fmaf(xs[(ic << 5) + px], wr[ic], acc);
        const int s = s0 + px;
        if (g == 0)
            out_ctr[(size_t)n * HW + s] = acc;
        else
            out_reg[((size_t)n * 4 + (g - 1)) * HW + s] = fmaxf(acc * stride, 0.f);
    }
}

// ---------------------------------------------------------------------------
// Host launcher
// ---------------------------------------------------------------------------
extern "C" void kernel_launch(void* const* d_in, const int* in_sizes, int n_in,
                              void* d_out, int out_size) {
    (void)in_sizes; (void)n_in; (void)out_size;

    const float* fpn[5];
    for (int i = 0; i < 5; ++i) fpn[i] = (const float*)d_in[i];
    const float* cls_conv_w  = (const float*)d_in[5];
    const float* cls_scale   = (const float*)d_in[6];
    const float* cls_bias    = (const float*)d_in[7];
    const float* cls_final_w = (const float*)d_in[8];
    const float* cls_final_b = (const float*)d_in[9];
    const float* reg_conv_w  = (const float*)d_in[10];
    const float* reg_scale   = (const float*)d_in[11];
    const float* reg_bias    = (const float*)d_in[12];
    const float* reg_final_w = (const float*)d_in[13];
    const float* reg_final_b = (const float*)d_in[14];
    float* out = (float*)d_out;

    float *bufA, *bufB, *wfc;
    uint32_t* wb;
    cudaGetSymbolAddress((void**)&bufA, g_bufA);
    cudaGetSymbolAddress((void**)&bufB, g_bufB);
    cudaGetSymbolAddress((void**)&wb,   g_wb);
    cudaGetSymbolAddress((void**)&wfc,  g_wfc);

    static bool attr_done = false;
    if (!attr_done) {
        cudaFuncSetAttribute(conv3x3_mma,
                             cudaFuncAttributeMaxDynamicSharedMemorySize,
                             SMEM_BYTES);
        attr_done = true;
    }

    const long HEADWORDS = 4L * 16 * 2 * 9 * 256 * 8;   // per head
    const long LAYERWORDS = HEADWORDS / 4;
    const long wtot = HEADWORDS;

    wsplit<<<(int)((wtot + 255) / 256), 256>>>(cls_conv_w, wb);
    wsplit<<<(int)((wtot + 255) / 256), 256>>>(reg_conv_w, wb + HEADWORDS);
    transpose_fc<<<(80 * 256 + 255) / 256, 256>>>(cls_final_w, wfc);

    const int Hs[5] = {128, 64, 32, 16, 8};
    const float strides[5] = {8.f, 16.f, 32.f, 64.f, 128.f};
    long HWs[5], clsOff[5], regOff[5], ctrOff[5];
    for (int l = 0; l < 5; ++l) HWs[l] = (long)Hs[l] * Hs[l];
    long off = 0;
    for (int l = 0; l < 5; ++l) { clsOff[l] = off; off += (long)NB * 80 * HWs[l]; }
    for (int l = 0; l < 5; ++l) { regOff[l] = off; off += (long)NB * 4 * HWs[l]; }
    for (int l = 0; l < 5; ++l) { ctrOff[l] = off; off += (long)NB * 1 * HWs[l]; }

    for (int l = 0; l < 5; ++l) {
        const int H = Hs[l], W = Hs[l];
        const int HW = H * W;
        dim3 grid((H / 8) * (W / 8), OCH / 64, NB);

        for (int head = 0; head < 2; ++head) {
            const float* src = fpn[l];
            const uint32_t* wbase = wb + head * HEADWORDS;
            const float* sc = (head == 0) ? cls_scale : reg_scale;
            const float* bi = (head == 0) ? cls_bias : reg_bias;
            for (int i = 0; i < 4; ++i) {
                float* dst = (i & 1) ? bufB : bufA;
                conv3x3_mma<<<grid, 128, SMEM_BYTES>>>(
                    src, wbase + i * LAYERWORDS,
                    sc + i * ICH, bi + i * ICH, dst, H, W);
                src = dst;
            }
            const int fgrid = NB * HW / 32;
            if (head == 0) {
                final_conv_cls<<<fgrid, 256>>>(src, wfc, cls_final_b,
                                               out + clsOff[l], HW);
            } else {
                final_conv_reg<<<fgrid, 256>>>(src, reg_final_w, reg_final_b,
                                               out + regOff[l], out + ctrOff[l],
                                               HW, strides[l]);
            }
        }
    }
}

// round 13
// speedup vs baseline: 2.3990x; 1.7121x over previous
#include <cuda_runtime.h>
#include <cuda_bf16.h>
#include <cstdint>

// ---------------------------------------------------------------------------
// FCOS decoder heads. Conv3x3 on tensor cores (mma.sync.m16n8k16.bf16),
// 3-term hi/lo bf16 split: W*X ~= Wh*Xh + Wl*Xh + Wh*Xl.
// Block: 256 threads / 8 warps; tile 64 oc x 256 px (16x16); K = 256ic x 9taps.
// Warp: 2 m-tiles (16 oc) x 8 n-tiles (8 px). Output: cls0..4, reg0..4, ctr0..4.
// ---------------------------------------------------------------------------

#define ICH 256
#define OCH 256
#define NB  4

// Scratch (no cudaMalloc allowed)
__device__ float g_bufA[(size_t)NB * ICH * 128 * 128];   // 64 MiB
__device__ float g_bufB[(size_t)NB * ICH * 128 * 128];   // 64 MiB
// packed bf16-pair words: [head][layer][chunk16][h(hi/lo)][tap9][oc256][w8]
__device__ uint32_t g_wb[(size_t)2 * 4 * 16 * 2 * 9 * 256 * 8];
__device__ float g_wfc[80 * 256];                        // cls final, [ic][oc]

// ---- helpers ---------------------------------------------------------------
__device__ __forceinline__ uint32_t packbf(__nv_bfloat16 a, __nv_bfloat16 b) {
    __nv_bfloat162 t(a, b);
    return *reinterpret_cast<uint32_t*>(&t);
}

__device__ __forceinline__ void mma16816(float* d, const uint32_t* a,
                                         const uint32_t* b) {
    asm volatile(
        "mma.sync.aligned.m16n8k16.row.col.f32.bf16.bf16.f32 "
        "{%0,%1,%2,%3},{%4,%5,%6,%7},{%8,%9},{%0,%1,%2,%3};"
        : "+f"(d[0]), "+f"(d[1]), "+f"(d[2]), "+f"(d[3])
        : "r"(a[0]), "r"(a[1]), "r"(a[2]), "r"(a[3]), "r"(b[0]), "r"(b[1]));
}

// ---------------------------------------------------------------------------
// Weight split/pack: fp32 (4, OC, IC, 3, 3) ->
//   words [(layer,chunk,h,tap,oc,w)] ; word = bf16(ic=2w) | bf16(ic=2w+1)<<16
// ---------------------------------------------------------------------------
__global__ void wsplit(const float* __restrict__ w, uint32_t* __restrict__ out) {
    long i = (long)blockIdx.x * blockDim.x + threadIdx.x;
    const long total = 4L * 16 * 2 * 9 * 256 * 8;
    if (i >= total) return;
    int wd = (int)(i & 7);
    long t = i >> 3;
    int oc = (int)(t & 255); t >>= 8;
    int tap = (int)(t % 9); t /= 9;
    int h = (int)(t & 1); t >>= 1;
    int chunk = (int)(t & 15); t >>= 4;
    int layer = (int)t;
    int ic0 = chunk * 16 + wd * 2;
    float v0 = w[(((long)(layer * 256 + oc) * 256 + ic0) * 9) + tap];
    float v1 = w[(((long)(layer * 256 + oc) * 256 + ic0 + 1) * 9) + tap];
    __nv_bfloat16 h0 = __float2bfloat16_rn(v0);
    __nv_bfloat16 h1 = __float2bfloat16_rn(v1);
    if (h == 0) {
        out[i] = packbf(h0, h1);
    } else {
        __nv_bfloat16 l0 = __float2bfloat16_rn(v0 - __bfloat162float(h0));
        __nv_bfloat16 l1 = __float2bfloat16_rn(v1 - __bfloat162float(h1));
        out[i] = packbf(l0, l1);
    }
}

// cls final weights: (80, 256) -> (256, 80)
__global__ void transpose_fc(const float* __restrict__ w,
                             float* __restrict__ wT) {
    int i = blockIdx.x * blockDim.x + threadIdx.x;
    if (i >= 80 * 256) return;
    int oc = i % 80;
    int ic = i / 80;
    wT[i] = w[oc * 256 + ic];
}

// ---------------------------------------------------------------------------
// conv3x3 + BN + ReLU via tensor cores.
// 256 threads, 8 warps: warp_m = wid&1, warp_n = wid>>1 (4 row-groups).
// Tile: 64 oc x 16x16 px. Halo 18x18. Smem rows padded to 12 words.
// sW: [h2][tap9][oc64][12w]  (h-stride 6912)
// sX: [h2][y18][x18][12w]    (h-stride 3888)
// ---------------------------------------------------------------------------
#define SW_WORDS (2 * 9 * 64 * 12)    // 13824
#define SX_WORDS (2 * 18 * 18 * 12)   // 7776
#define SMEM_BYTES ((SW_WORDS + SX_WORDS) * 4)   // 86400

__global__ __launch_bounds__(256)
void conv3x3_mma(const float* __restrict__ in,
                 const uint32_t* __restrict__ wb,   // per-layer base
                 const float* __restrict__ scale,
                 const float* __restrict__ bias,
                 float* __restrict__ out,
                 int H, int W) {
    extern __shared__ uint32_t sm[];
    uint32_t* sW = sm;
    uint32_t* sX = sm + SW_WORDS;

    const int tid = threadIdx.x;
    const int lane = tid & 31;
    const int wid = tid >> 5;
    const int warp_m = wid & 1;
    const int warp_n = wid >> 1;           // 0..3
    const int lq = lane >> 2;              // 0..7
    const int lr = lane & 3;               // 0..3

    const int tilesX = (W + 15) >> 4;
    const int tileX = blockIdx.x % tilesX;
    const int tileY = blockIdx.x / tilesX;
    const int ocb = blockIdx.y << 6;
    const int n = blockIdx.z;
    const int gx0 = tileX << 4;
    const int gy0 = tileY << 4;
    const int HW = H * W;

    const float* inN = in + (size_t)n * ICH * HW;

    float acc[2][8][4];
#pragma unroll
    for (int mi = 0; mi < 2; ++mi)
#pragma unroll
        for (int ni = 0; ni < 8; ++ni)
#pragma unroll
            for (int k = 0; k < 4; ++k) acc[mi][ni][k] = 0.f;

    for (int chunk = 0; chunk < 16; ++chunk) {
        const int ic0 = chunk << 4;
        // ---- weight fill: 2*9*64*8 = 9216 words, coalesced ----
        const uint32_t* wsrc = wb + (size_t)chunk * (2 * 9 * 256 * 8);
        for (int i = tid; i < 9216; i += 256) {
            int wd = i & 7;
            int t = i >> 3;
            int oc = t & 63; t >>= 6;        // t: 0..17
            int tap = t % 9;
            int h = t / 9;
            sW[((h * 9 + tap) * 64 + oc) * 12 + wd] =
                wsrc[((size_t)(h * 9 + tap) * 256 + ocb + oc) * 8 + wd];
        }
        // ---- halo fill: 18x18 px, 8 ic-pair words, hi+lo (px-major) ----
        for (int i = tid; i < 2592; i += 256) {
            int px = i % 324;
            int wd = i / 324;
            int y = px / 18;
            int x = px % 18;
            int gy = gy0 + y - 1;
            int gx = gx0 + x - 1;
            float v0 = 0.f, v1 = 0.f;
            if ((unsigned)gy < (unsigned)H && (unsigned)gx < (unsigned)W) {
                const float* p = inN + (size_t)(ic0 + 2 * wd) * HW + gy * W + gx;
                v0 = p[0];
                v1 = p[HW];
            }
            __nv_bfloat16 h0 = __float2bfloat16_rn(v0);
            __nv_bfloat16 h1 = __float2bfloat16_rn(v1);
            __nv_bfloat16 l0 = __float2bfloat16_rn(v0 - __bfloat162float(h0));
            __nv_bfloat16 l1 = __float2bfloat16_rn(v1 - __bfloat162float(h1));
            sX[px * 12 + wd] = packbf(h0, h1);
            sX[3888 + px * 12 + wd] = packbf(l0, l1);
        }
        __syncthreads();

        int dy = 0, dx = 0;
        for (int tap = 0; tap < 9; ++tap) {
            // A fragments (hi, lo) for 2 m-tiles
            uint32_t ah[2][4], al[2][4];
#pragma unroll
            for (int mi = 0; mi < 2; ++mi) {
                const int ocr = warp_m * 32 + mi * 16;
                const uint32_t* pw = sW + (tap * 64 + ocr) * 12;
                ah[mi][0] = pw[lq * 12 + lr];
                ah[mi][1] = pw[(lq + 8) * 12 + lr];
                ah[mi][2] = pw[lq * 12 + lr + 4];
                ah[mi][3] = pw[(lq + 8) * 12 + lr + 4];
                const uint32_t* pl = pw + 6912;   // h=1
                al[mi][0] = pl[lq * 12 + lr];
                al[mi][1] = pl[(lq + 8) * 12 + lr];
                al[mi][2] = pl[lq * 12 + lr + 4];
                al[mi][3] = pl[(lq + 8) * 12 + lr + 4];
            }
            // 8 n-tiles: row = warp_n*4 + (ni>>1), x-half = ni&1
#pragma unroll
            for (int ni = 0; ni < 8; ++ni) {
                const int y = warp_n * 4 + (ni >> 1) + dy;
                const int x = (ni & 1) * 8 + lq + dx;
                const uint32_t* px_ = sX + (y * 18 + x) * 12;
                uint32_t bh[2], bl[2];
                bh[0] = px_[lr];
                bh[1] = px_[lr + 4];
                bl[0] = px_[3888 + lr];
                bl[1] = px_[3888 + lr + 4];
#pragma unroll
                for (int mi = 0; mi < 2; ++mi) {
                    mma16816(acc[mi][ni], ah[mi], bh);
                    mma16816(acc[mi][ni], al[mi], bh);
                    mma16816(acc[mi][ni], ah[mi], bl);
                }
            }
            if (++dx == 3) { dx = 0; ++dy; }
        }
        __syncthreads();
    }

    // ---- epilogue: BN fold + ReLU ----
#pragma unroll
    for (int mi = 0; mi < 2; ++mi) {
        const int oc0 = ocb + warp_m * 32 + mi * 16 + lq;
        const int oc1 = oc0 + 8;
        const float s0 = scale[oc0], b0 = bias[oc0];
        const float s1 = scale[oc1], b1 = bias[oc1];
        float* o0 = out + ((size_t)n * OCH + oc0) * HW;
        float* o1 = out + ((size_t)n * OCH + oc1) * HW;
#pragma unroll
        for (int ni = 0; ni < 8; ++ni) {
            const int py = warp_n * 4 + (ni >> 1);
            const int pxx = (ni & 1) * 8 + lr * 2;
            if (gy0 + py < H && gx0 + pxx < W) {
                const size_t pix = (size_t)(gy0 + py) * W + gx0 + pxx;
                float2 v0, v1;
                v0.x = fmaxf(fmaf(acc[mi][ni][0], s0, b0), 0.f);
                v0.y = fmaxf(fmaf(acc[mi][ni][1], s0, b0), 0.f);
                v1.x = fmaxf(fmaf(acc[mi][ni][2], s1, b1), 0.f);
                v1.y = fmaxf(fmaf(acc[mi][ni][3], s1, b1), 0.f);
                *(float2*)(o0 + pix) = v0;
                *(float2*)(o1 + pix) = v1;
            }
        }
    }
}

// ---------------------------------------------------------------------------
// cls final: 1x1 conv 256 -> 80 (+bias). Block: 32 pixels, 8 groups x 10 oc.
// ---------------------------------------------------------------------------
__global__ __launch_bounds__(256)
void final_conv_cls(const float* __restrict__ in,
                    const float* __restrict__ wT,
                    const float* __restrict__ b,
                    float* __restrict__ out, int HW) {
    __shared__ float xs[8192];
    __shared__ float ws[32 * 80];

    const int tid = threadIdx.x;
    const long p0 = (long)blockIdx.x * 32;
    const int n = (int)(p0 / HW);
    const int s0 = (int)(p0 % HW);
    const float* inN = in + (size_t)n * 256 * HW + s0;

    for (int i = tid; i < 8192; i += 256) {
        int ic = i >> 5, p = i & 31;
        xs[i] = inN[(size_t)ic * HW + p];
    }

    const int px = tid & 31;
    const int g = tid >> 5;
    const int oc0 = g * 10;
    float acc[10];
#pragma unroll
    for (int j = 0; j < 10; ++j) acc[j] = b[oc0 + j];

    for (int ic0 = 0; ic0 < 256; ic0 += 32) {
        __syncthreads();
        for (int i = tid; i < 2560; i += 256) ws[i] = wT[ic0 * 80 + i];
        __syncthreads();
        for (int icc = 0; icc < 32; ++icc) {
            float x = xs[((ic0 + icc) << 5) + px];
            const float* wr = &ws[icc * 80 + oc0];
#pragma unroll
            for (int j = 0; j < 10; ++j) acc[j] = fmaf(x, wr[j], acc[j]);
        }
    }

    const int s = s0 + px;
#pragma unroll
    for (int j = 0; j < 10; ++j)
        out[((size_t)n * 80 + oc0 + j) * HW + s] = acc[j];
}

// ---------------------------------------------------------------------------
// reg final: 1x1 conv 256 -> 5 (+bias). ch0 -> centerness (raw),
// ch1..4 -> max(raw * stride, 0). w layout [oc(5)][ic(256)].
// ---------------------------------------------------------------------------
__global__ __launch_bounds__(256)
void final_conv_reg(const float* __restrict__ in,
                    const float* __restrict__ w,
                    const float* __restrict__ b,
                    float* __restrict__ out_reg,
                    float* __restrict__ out_ctr,
                    int HW, float stride) {
    __shared__ float xs[8192];
    __shared__ float ws[5 * 256];

    const int tid = threadIdx.x;
    for (int i = tid; i < 1280; i += 256) ws[i] = w[i];

    const long p0 = (long)blockIdx.x * 32;
    const int n = (int)(p0 / HW);
    const int s0 = (int)(p0 % HW);
    const float* inN = in + (size_t)n * 256 * HW + s0;
    for (int i = tid; i < 8192; i += 256) {
        int ic = i >> 5, p = i & 31;
        xs[i] = inN[(size_t)ic * HW + p];
    }
    __syncthreads();

    const int px = tid & 31;
    const int g = tid >> 5;
    if (g < 5) {
        float acc = b[g];
        const float* wr = &ws[g * 256];
        for (int ic = 0; ic < 256; ++ic)
            acc = fmaf(xs[(ic << 5) + px], wr[ic], acc);
        const int s = s0 + px;
        if (g == 0)
            out_ctr[(size_t)n * HW + s] = acc;
        else
            out_reg[((size_t)n * 4 + (g - 1)) * HW + s] = fmaxf(acc * stride, 0.f);
    }
}

// ---------------------------------------------------------------------------
// Host launcher
// ---------------------------------------------------------------------------
extern "C" void kernel_launch(void* const* d_in, const int* in_sizes, int n_in,
                              void* d_out, int out_size) {
    (void)in_sizes; (void)n_in; (void)out_size;

    const float* fpn[5];
    for (int i = 0; i < 5; ++i) fpn[i] = (const float*)d_in[i];
    const float* cls_conv_w  = (const float*)d_in[5];
    const float* cls_scale   = (const float*)d_in[6];
    const float* cls_bias    = (const float*)d_in[7];
    const float* cls_final_w = (const float*)d_in[8];
    const float* cls_final_b = (const float*)d_in[9];
    const float* reg_conv_w  = (const float*)d_in[10];
    const float* reg_scale   = (const float*)d_in[11];
    const float* reg_bias    = (const float*)d_in[12];
    const float* reg_final_w = (const float*)d_in[13];
    const float* reg_final_b = (const float*)d_in[14];
    float* out = (float*)d_out;

    float *bufA, *bufB, *wfc;
    uint32_t* wb;
    cudaGetSymbolAddress((void**)&bufA, g_bufA);
    cudaGetSymbolAddress((void**)&bufB, g_bufB);
    cudaGetSymbolAddress((void**)&wb,   g_wb);
    cudaGetSymbolAddress((void**)&wfc,  g_wfc);

    static bool attr_done = false;
    if (!attr_done) {
        cudaFuncSetAttribute(conv3x3_mma,
                             cudaFuncAttributeMaxDynamicSharedMemorySize,
                             SMEM_BYTES);
        attr_done = true;
    }

    const long HEADWORDS = 4L * 16 * 2 * 9 * 256 * 8;   // per head
    const long LAYERWORDS = HEADWORDS / 4;
    const long wtot = HEADWORDS;

    wsplit<<<(int)((wtot + 255) / 256), 256>>>(cls_conv_w, wb);
    wsplit<<<(int)((wtot + 255) / 256), 256>>>(reg_conv_w, wb + HEADWORDS);
    transpose_fc<<<(80 * 256 + 255) / 256, 256>>>(cls_final_w, wfc);

    const int Hs[5] = {128, 64, 32, 16, 8};
    const float strides[5] = {8.f, 16.f, 32.f, 64.f, 128.f};
    long HWs[5], clsOff[5], regOff[5], ctrOff[5];
    for (int l = 0; l < 5; ++l) HWs[l] = (long)Hs[l] * Hs[l];
    long off = 0;
    for (int l = 0; l < 5; ++l) { clsOff[l] = off; off += (long)NB * 80 * HWs[l]; }
    for (int l = 0; l < 5; ++l) { regOff[l] = off; off += (long)NB * 4 * HWs[l]; }
    for (int l = 0; l < 5; ++l) { ctrOff[l] = off; off += (long)NB * 1 * HWs[l]; }

    for (int l = 0; l < 5; ++l) {
        const int H = Hs[l], W = Hs[l];
        const int HW = H * W;
        const int tX = (W + 15) / 16, tY = (H + 15) / 16;
        dim3 grid(tX * tY, OCH / 64, NB);

        for (int head = 0; head < 2; ++head) {
            const float* src = fpn[l];
            const uint32_t* wbase = wb + head * HEADWORDS;
            const float* sc = (head == 0) ? cls_scale : reg_scale;
            const float* bi = (head == 0) ? cls_bias : reg_bias;
            for (int i = 0; i < 4; ++i) {
                float* dst = (i & 1) ? bufB : bufA;
                conv3x3_mma<<<grid, 256, SMEM_BYTES>>>(
                    src, wbase + i * LAYERWORDS,
                    sc + i * ICH, bi + i * ICH, dst, H, W);
                src = dst;
            }
            const int fgrid = NB * HW / 32;
            if (head == 0) {
                final_conv_cls<<<fgrid, 256>>>(src, wfc, cls_final_b,
                                               out + clsOff[l], HW);
            } else {
                final_conv_reg<<<fgrid, 256>>>(src, reg_final_w, reg_final_b,
                                               out + regOff[l], out + ctrOff[l],
                                               HW, strides[l]);
            }
        }
    }
}

// round 14
// speedup vs baseline: 2.7026x; 1.1265x over previous
#include <cuda_runtime.h>
#include <cuda_bf16.h>
#include <cstdint>

// ---------------------------------------------------------------------------
// FCOS decoder heads. Conv3x3 on tensor cores (mma.sync.m16n8k16.bf16),
// 3-term hi/lo bf16 split: W*X ~= Wh*Xh + Wl*Xh + Wh*Xl.
// Block: 256 threads / 8 warps; tile 64 oc x 16x16 px; both heads merged in
// one launch (grid.z = 2 heads x 4 batch). Fragments via ldmatrix, weight
// fills via cp.async. Output order: cls0..4, reg0..4, ctr0..4.
// ---------------------------------------------------------------------------

#define ICH 256
#define OCH 256
#define NB  4

// Scratch (no cudaMalloc allowed). Buffers hold both heads: [head][n][c][hw].
__device__ float g_bufA[(size_t)2 * NB * ICH * 128 * 128];   // 128 MiB
__device__ float g_bufB[(size_t)2 * NB * ICH * 128 * 128];   // 128 MiB
// packed bf16-pair words: [head][layer][chunk16][h(hi/lo)][tap9][oc256][w8]
__device__ uint32_t g_wb[(size_t)2 * 4 * 16 * 2 * 9 * 256 * 8];
__device__ float g_wfc[80 * 256];                            // cls final, [ic][oc]

// ---- helpers ---------------------------------------------------------------
__device__ __forceinline__ uint32_t packbf(__nv_bfloat16 a, __nv_bfloat16 b) {
    __nv_bfloat162 t(a, b);
    return *reinterpret_cast<uint32_t*>(&t);
}

__device__ __forceinline__ void mma16816(float* d, const uint32_t* a,
                                         const uint32_t* b) {
    asm volatile(
        "mma.sync.aligned.m16n8k16.row.col.f32.bf16.bf16.f32 "
        "{%0,%1,%2,%3},{%4,%5,%6,%7},{%8,%9},{%0,%1,%2,%3};"
        : "+f"(d[0]), "+f"(d[1]), "+f"(d[2]), "+f"(d[3])
        : "r"(a[0]), "r"(a[1]), "r"(a[2]), "r"(a[3]), "r"(b[0]), "r"(b[1]));
}

__device__ __forceinline__ void ldsm4(uint32_t* r, uint32_t saddr) {
    asm volatile(
        "ldmatrix.sync.aligned.m8n8.x4.shared.b16 {%0,%1,%2,%3}, [%4];"
        : "=r"(r[0]), "=r"(r[1]), "=r"(r[2]), "=r"(r[3]) : "r"(saddr));
}

__device__ __forceinline__ void cpasync16(uint32_t sdst, const void* gsrc) {
    asm volatile("cp.async.cg.shared.global [%0], [%1], 16;"
                 :: "r"(sdst), "l"(gsrc));
}

// ---------------------------------------------------------------------------
// Weight split/pack: fp32 (4, OC, IC, 3, 3) ->
//   words [(layer,chunk,h,tap,oc,w)] ; word = bf16(ic=2w) | bf16(ic=2w+1)<<16
// ---------------------------------------------------------------------------
__global__ void wsplit(const float* __restrict__ w, uint32_t* __restrict__ out) {
    long i = (long)blockIdx.x * blockDim.x + threadIdx.x;
    const long total = 4L * 16 * 2 * 9 * 256 * 8;
    if (i >= total) return;
    int wd = (int)(i & 7);
    long t = i >> 3;
    int oc = (int)(t & 255); t >>= 8;
    int tap = (int)(t % 9); t /= 9;
    int h = (int)(t & 1); t >>= 1;
    int chunk = (int)(t & 15); t >>= 4;
    int layer = (int)t;
    int ic0 = chunk * 16 + wd * 2;
    float v0 = w[(((long)(layer * 256 + oc) * 256 + ic0) * 9) + tap];
    float v1 = w[(((long)(layer * 256 + oc) * 256 + ic0 + 1) * 9) + tap];
    __nv_bfloat16 h0 = __float2bfloat16_rn(v0);
    __nv_bfloat16 h1 = __float2bfloat16_rn(v1);
    if (h == 0) {
        out[i] = packbf(h0, h1);
    } else {
        __nv_bfloat16 l0 = __float2bfloat16_rn(v0 - __bfloat162float(h0));
        __nv_bfloat16 l1 = __float2bfloat16_rn(v1 - __bfloat162float(h1));
        out[i] = packbf(l0, l1);
    }
}

// cls final weights: (80, 256) -> (256, 80)
__global__ void transpose_fc(const float* __restrict__ w,
                             float* __restrict__ wT) {
    int i = blockIdx.x * blockDim.x + threadIdx.x;
    if (i >= 80 * 256) return;
    int oc = i % 80;
    int ic = i / 80;
    wT[i] = w[oc * 256 + ic];
}

// ---------------------------------------------------------------------------
// conv3x3 + BN + ReLU via tensor cores (ldmatrix + cp.async).
// 256 threads, 8 warps: warp_m = wid&1, warp_n = wid>>1 (4 row-groups).
// Tile: 64 oc x 16x16 px. Halo 18x18. Smem rows padded to 12 words.
// sW: [h2][tap9][oc64][12w]  (h-stride 6912 words)
// sX: [h2][y18][x18][12w]    (h-stride 3888 words)
// grid.z encodes head (z>>2) and batch n (z&3).
// ---------------------------------------------------------------------------
#define SW_WORDS (2 * 9 * 64 * 12)    // 13824
#define SX_WORDS (2 * 18 * 18 * 12)   // 7776
#define SMEM_BYTES ((SW_WORDS + SX_WORDS) * 4)   // 86400

__global__ __launch_bounds__(256, 2)
void conv3x3_mma(const float* __restrict__ src0,   // head 0 input (n-major)
                 const float* __restrict__ src1,   // head 1 input
                 const uint32_t* __restrict__ wb0, // head 0 layer weights
                 const uint32_t* __restrict__ wb1, // head 1 layer weights
                 const float* __restrict__ sc0, const float* __restrict__ sc1,
                 const float* __restrict__ bi0, const float* __restrict__ bi1,
                 float* __restrict__ dstbase,      // + head*headStride
                 size_t headStride,
                 int H, int W) {
    extern __shared__ uint32_t sm[];
    uint32_t* sW = sm;
    uint32_t* sX = sm + SW_WORDS;
    const uint32_t sW32 = (uint32_t)__cvta_generic_to_shared(sW);
    const uint32_t sX32 = (uint32_t)__cvta_generic_to_shared(sX);

    const int tid = threadIdx.x;
    const int lane = tid & 31;
    const int wid = tid >> 5;
    const int warp_m = wid & 1;
    const int warp_n = wid >> 1;           // 0..3
    const int lq = lane >> 2;              // 0..7
    const int lr = lane & 3;               // 0..3

    const int tilesX = (W + 15) >> 4;
    const int tileX = blockIdx.x % tilesX;
    const int tileY = blockIdx.x / tilesX;
    const int ocb = blockIdx.y << 6;
    const int z = blockIdx.z;
    const int n = z & 3;
    const int head = z >> 2;
    const int gx0 = tileX << 4;
    const int gy0 = tileY << 4;
    const int HW = H * W;

    const float* in = head ? src1 : src0;
    const uint32_t* wb = head ? wb1 : wb0;
    const float* inN = in + (size_t)n * ICH * HW;

    // per-thread ldmatrix byte offsets
    const uint32_t aoff = ((lane & 15) * 12 + (lane >> 4) * 4) * 4;
    const uint32_t boff0 = (((lane >> 4) * 8 + (lane & 7)) * 12 +
                            ((lane >> 3) & 1) * 4) * 4;

    float acc[2][8][4];
#pragma unroll
    for (int mi = 0; mi < 2; ++mi)
#pragma unroll
        for (int ni = 0; ni < 8; ++ni)
#pragma unroll
            for (int k = 0; k < 4; ++k) acc[mi][ni][k] = 0.f;

    for (int chunk = 0; chunk < 16; ++chunk) {
        const int ic0 = chunk << 4;
        // ---- weight fill via cp.async: 2304 x 16B ----
        const uint32_t* wsrc = wb + (size_t)chunk * (2 * 9 * 256 * 8);
        for (int i = tid; i < 2304; i += 256) {
            int wd4 = (i & 1) * 4;
            int t = i >> 1;
            int oc = t & 63; t >>= 6;        // t: 0..17
            int tap = t % 9;
            int h = t / 9;
            uint32_t dst = sW32 + ((((h * 9 + tap) * 64 + oc) * 12 + wd4) << 2);
            cpasync16(dst, wsrc + ((size_t)((h * 9 + tap) * 256) + ocb + oc) * 8 + wd4);
        }
        asm volatile("cp.async.commit_group;");

        // ---- halo fill: 18x18 px, 8 ic-pair words, hi+lo (px-major) ----
        for (int i = tid; i < 2592; i += 256) {
            int px = i % 324;
            int wd = i / 324;
            int y = px / 18;
            int x = px % 18;
            int gy = gy0 + y - 1;
            int gx = gx0 + x - 1;
            float v0 = 0.f, v1 = 0.f;
            if ((unsigned)gy < (unsigned)H && (unsigned)gx < (unsigned)W) {
                const float* p = inN + (size_t)(ic0 + 2 * wd) * HW + gy * W + gx;
                v0 = p[0];
                v1 = p[HW];
            }
            __nv_bfloat16 h0 = __float2bfloat16_rn(v0);
            __nv_bfloat16 h1 = __float2bfloat16_rn(v1);
            __nv_bfloat16 l0 = __float2bfloat16_rn(v0 - __bfloat162float(h0));
            __nv_bfloat16 l1 = __float2bfloat16_rn(v1 - __bfloat162float(h1));
            sX[px * 12 + wd] = packbf(h0, h1);
            sX[3888 + px * 12 + wd] = packbf(l0, l1);
        }
        asm volatile("cp.async.wait_group 0;" ::: "memory");
        __syncthreads();

        int dy = 0, dx = 0;
        for (int tap = 0; tap < 9; ++tap) {
            // A fragments (hi, lo) for 2 m-tiles via ldmatrix.x4
            uint32_t ah[2][4], al[2][4];
#pragma unroll
            for (int mi = 0; mi < 2; ++mi) {
                uint32_t a0 = sW32 +
                    (((tap * 64 + warp_m * 32 + mi * 16) * 12) << 2) + aoff;
                ldsm4(ah[mi], a0);
                ldsm4(al[mi], a0 + (6912 << 2));
            }
            // 4 pairs of n-tiles; each ldmatrix.x4 loads both x-halves
#pragma unroll
            for (int p = 0; p < 4; ++p) {
                uint32_t b0 = sX32 +
                    ((((warp_n * 4 + p + dy) * 18 + dx) * 12) << 2) + boff0;
                uint32_t bh[4], bl[4];
                ldsm4(bh, b0);
                ldsm4(bl, b0 + (3888 << 2));
#pragma unroll
                for (int mi = 0; mi < 2; ++mi) {
                    mma16816(acc[mi][2 * p],     ah[mi], bh);
                    mma16816(acc[mi][2 * p],     al[mi], bh);
                    mma16816(acc[mi][2 * p],     ah[mi], bl);
                    mma16816(acc[mi][2 * p + 1], ah[mi], bh + 2);
                    mma16816(acc[mi][2 * p + 1], al[mi], bh + 2);
                    mma16816(acc[mi][2 * p + 1], ah[mi], bl + 2);
                }
            }
            if (++dx == 3) { dx = 0; ++dy; }
        }
        __syncthreads();
    }

    // ---- epilogue: BN fold + ReLU ----
    const float* scale = head ? sc1 : sc0;
    const float* bias  = head ? bi1 : bi0;
    float* outN = dstbase + (size_t)head * headStride;
#pragma unroll
    for (int mi = 0; mi < 2; ++mi) {
        const int oc0 = ocb + warp_m * 32 + mi * 16 + lq;
        const int oc1 = oc0 + 8;
        const float s0 = scale[oc0], b0 = bias[oc0];
        const float s1 = scale[oc1], b1 = bias[oc1];
        float* o0 = outN + ((size_t)n * OCH + oc0) * HW;
        float* o1 = outN + ((size_t)n * OCH + oc1) * HW;
#pragma unroll
        for (int ni = 0; ni < 8; ++ni) {
            const int py = warp_n * 4 + (ni >> 1);
            const int pxx = (ni & 1) * 8 + lr * 2;
            if (gy0 + py < H && gx0 + pxx < W) {
                const size_t pix = (size_t)(gy0 + py) * W + gx0 + pxx;
                float2 v0, v1;
                v0.x = fmaxf(fmaf(acc[mi][ni][0], s0, b0), 0.f);
                v0.y = fmaxf(fmaf(acc[mi][ni][1], s0, b0), 0.f);
                v1.x = fmaxf(fmaf(acc[mi][ni][2], s1, b1), 0.f);
                v1.y = fmaxf(fmaf(acc[mi][ni][3], s1, b1), 0.f);
                *(float2*)(o0 + pix) = v0;
                *(float2*)(o1 + pix) = v1;
            }
        }
    }
}

// ---------------------------------------------------------------------------
// cls final: 1x1 conv 256 -> 80 (+bias). Block: 32 pixels, 8 groups x 10 oc.
// ---------------------------------------------------------------------------
__global__ __launch_bounds__(256)
void final_conv_cls(const float* __restrict__ in,
                    const float* __restrict__ wT,
                    const float* __restrict__ b,
                    float* __restrict__ out, int HW) {
    __shared__ float xs[8192];
    __shared__ float ws[32 * 80];

    const int tid = threadIdx.x;
    const long p0 = (long)blockIdx.x * 32;
    const int n = (int)(p0 / HW);
    const int s0 = (int)(p0 % HW);
    const float* inN = in + (size_t)n * 256 * HW + s0;

    for (int i = tid; i < 8192; i += 256) {
        int ic = i >> 5, p = i & 31;
        xs[i] = inN[(size_t)ic * HW + p];
    }

    const int px = tid & 31;
    const int g = tid >> 5;
    const int oc0 = g * 10;
    float acc[10];
#pragma unroll
    for (int j = 0; j < 10; ++j) acc[j] = b[oc0 + j];

    for (int ic0 = 0; ic0 < 256; ic0 += 32) {
        __syncthreads();
        for (int i = tid; i < 2560; i += 256) ws[i] = wT[ic0 * 80 + i];
        __syncthreads();
        for (int icc = 0; icc < 32; ++icc) {
            float x = xs[((ic0 + icc) << 5) + px];
            const float* wr = &ws[icc * 80 + oc0];
#pragma unroll
            for (int j = 0; j < 10; ++j) acc[j] = fmaf(x, wr[j], acc[j]);
        }
    }

    const int s = s0 + px;
#pragma unroll
    for (int j = 0; j < 10; ++j)
        out[((size_t)n * 80 + oc0 + j) * HW + s] = acc[j];
}

// ---------------------------------------------------------------------------
// reg final: 1x1 conv 256 -> 5 (+bias). ch0 -> centerness (raw),
// ch1..4 -> max(raw * stride, 0). w layout [oc(5)][ic(256)].
// ---------------------------------------------------------------------------
__global__ __launch_bounds__(256)
void final_conv_reg(const float* __restrict__ in,
                    const float* __restrict__ w,
                    const float* __restrict__ b,
                    float* __restrict__ out_reg,
                    float* __restrict__ out_ctr,
                    int HW, float stride) {
    __shared__ float xs[8192];
    __shared__ float ws[5 * 256];

    const int tid = threadIdx.x;
    for (int i = tid; i < 1280; i += 256) ws[i] = w[i];

    const long p0 = (long)blockIdx.x * 32;
    const int n = (int)(p0 / HW);
    const int s0 = (int)(p0 % HW);
    const float* inN = in + (size_t)n * 256 * HW + s0;
    for (int i = tid; i < 8192; i += 256) {
        int ic = i >> 5, p = i & 31;
        xs[i] = inN[(size_t)ic * HW + p];
    }
    __syncthreads();

    const int px = tid & 31;
    const int g = tid >> 5;
    if (g < 5) {
        float acc = b[g];
        const float* wr = &ws[g * 256];
        for (int ic = 0; ic < 256; ++ic)
            acc = fmaf(xs[(ic << 5) + px], wr[ic], acc);
        const int s = s0 + px;
        if (g == 0)
            out_ctr[(size_t)n * HW + s] = acc;
        else
            out_reg[((size_t)n * 4 + (g - 1)) * HW + s] = fmaxf(acc * stride, 0.f);
    }
}

// ---------------------------------------------------------------------------
// Host launcher
// ---------------------------------------------------------------------------
extern "C" void kernel_launch(void* const* d_in, const int* in_sizes, int n_in,
                              void* d_out, int out_size) {
    (void)in_sizes; (void)n_in; (void)out_size;

    const float* fpn[5];
    for (int i = 0; i < 5; ++i) fpn[i] = (const float*)d_in[i];
    const float* cls_conv_w  = (const float*)d_in[5];
    const float* cls_scale   = (const float*)d_in[6];
    const float* cls_bias    = (const float*)d_in[7];
    const float* cls_final_w = (const float*)d_in[8];
    const float* cls_final_b = (const float*)d_in[9];
    const float* reg_conv_w  = (const float*)d_in[10];
    const float* reg_scale   = (const float*)d_in[11];
    const float* reg_bias    = (const float*)d_in[12];
    const float* reg_final_w = (const float*)d_in[13];
    const float* reg_final_b = (const float*)d_in[14];
    float* out = (float*)d_out;

    float *bufA, *bufB, *wfc;
    uint32_t* wb;
    cudaGetSymbolAddress((void**)&bufA, g_bufA);
    cudaGetSymbolAddress((void**)&bufB, g_bufB);
    cudaGetSymbolAddress((void**)&wb,   g_wb);
    cudaGetSymbolAddress((void**)&wfc,  g_wfc);

    cudaFuncSetAttribute(conv3x3_mma,
                         cudaFuncAttributeMaxDynamicSharedMemorySize,
                         SMEM_BYTES);

    const long HEADWORDS = 4L * 16 * 2 * 9 * 256 * 8;   // per head
    const long LAYERWORDS = HEADWORDS / 4;
    const long wtot = HEADWORDS;

    wsplit<<<(int)((wtot + 255) / 256), 256>>>(cls_conv_w, wb);
    wsplit<<<(int)((wtot + 255) / 256), 256>>>(reg_conv_w, wb + HEADWORDS);
    transpose_fc<<<(80 * 256 + 255) / 256, 256>>>(cls_final_w, wfc);

    const int Hs[5] = {128, 64, 32, 16, 8};
    const float strides[5] = {8.f, 16.f, 32.f, 64.f, 128.f};
    long HWs[5], clsOff[5], regOff[5], ctrOff[5];
    for (int l = 0; l < 5; ++l) HWs[l] = (long)Hs[l] * Hs[l];
    long off = 0;
    for (int l = 0; l < 5; ++l) { clsOff[l] = off; off += (long)NB * 80 * HWs[l]; }
    for (int l = 0; l < 5; ++l) { regOff[l] = off; off += (long)NB * 4 * HWs[l]; }
    for (int l = 0; l < 5; ++l) { ctrOff[l] = off; off += (long)NB * 1 * HWs[l]; }

    for (int l = 0; l < 5; ++l) {
        const int H = Hs[l], W = Hs[l];
        const int HW = H * W;
        const size_t headStride = (size_t)NB * ICH * HW;
        const int tX = (W + 15) / 16, tY = (H + 15) / 16;
        dim3 grid(tX * tY, OCH / 64, NB * 2);

        // 4 merged conv layers (both heads per launch)
        const float* s0 = fpn[l];
        const float* s1 = fpn[l];
        float* dst = nullptr;
        for (int i = 0; i < 4; ++i) {
            dst = (i & 1) ? bufB : bufA;
            conv3x3_mma<<<grid, 256, SMEM_BYTES>>>(
                s0, s1,
                wb + 0 * HEADWORDS + i * LAYERWORDS,
                wb + 1 * HEADWORDS + i * LAYERWORDS,
                cls_scale + i * ICH, reg_scale + i * ICH,
                cls_bias + i * ICH,  reg_bias + i * ICH,
                dst, headStride, H, W);
            s0 = dst;                 // head 0 region
            s1 = dst + headStride;    // head 1 region
        }

        const int fgrid = NB * HW / 32;
        final_conv_cls<<<fgrid, 256>>>(s0, wfc, cls_final_b,
                                       out + clsOff[l], HW);
        final_conv_reg<<<fgrid, 256>>>(s1, reg_final_w, reg_final_b,
                                       out + regOff[l], out + ctrOff[l],
                                       HW, strides[l]);
    }
}